// round 7
// baseline (speedup 1.0000x reference)
#include <cuda_runtime.h>

// ---------------------------------------------------------------------------
// TNModel binary-tree TN, B=65536. Round 7:
//  - main kernel: T1=64, 8 CTAs/SM (same 16 warps/SM, finer wave granularity
//    to cut the 0.46-wave quantization tail), weight-prefetch pipeline kept.
//  - merge kernel: all 16 global loads hoisted upfront (MLP 16) to cover
//    DRAM latency; grid 512 x 128.
// ---------------------------------------------------------------------------

#define NB       65536
#define HALF     (NB / 2)            // 32768
#define T1       64                  // threads, kernel 1
#define BLK_E    (HALF / T1)         // 512 blocks per eighth
#define NBLOCKS1 (8 * BLK_E)         // 4096
#define T2       128                 // threads, kernel 2
#define NBLOCKS2 (NB / T2)           // 512 (1 sample/thread)

// eighth-tree shared-memory float offsets
#define E7 0                      // 16 x 16   =  256
#define E6 (E7 + 256)             //  8 x 128  = 1024
#define E5 (E6 + 1024)            //  4 x 512  = 2048
#define E4 (E5 + 2048)            //  2 x 512  = 1024
#define E3 (E4 + 1024)            //  1 x 512  =  512
#define SMEM1_FLOATS (E3 + 512)   // 4864 floats = 19456 bytes

typedef unsigned long long ull;

__device__ float4 g_ebuf[8 * NB * 2];   // [eighth][sample][2 x float4]

__device__ __forceinline__ ull ffma2(ull a, ull b, ull c) {
    ull d;
    asm("fma.rn.f32x2 %0, %1, %2, %3;" : "=l"(d) : "l"(a), "l"(b), "l"(c));
    return d;
}
__device__ __forceinline__ ull bcast2(float x) {
    ull r;
    asm("mov.b64 %0, {%1, %1};" : "=l"(r) : "f"(x));
    return r;
}
__device__ __forceinline__ void unpack2(ull v, float& lo, float& hi) {
    asm("mov.b64 {%0, %1}, %2;" : "=f"(lo), "=f"(hi) : "l"(v));
}
__device__ __forceinline__ void cp8(float* d, const float* s) {
#pragma unroll
    for (int k = 0; k < 8; ++k) d[k] = s[k];
}

// leaf for two samples sharing W (16 floats)
__device__ __forceinline__ void leaf2(float4 qa, float4 qb,
                                      const float* __restrict__ w,
                                      float* hA, float* hB) {
    ull cA0 = 0, cA1 = 0, cB0 = 0, cB1 = 0;
    float eA[2] = {qa.x, qa.y}, oA[2] = {qa.z, qa.w};
    float eB[2] = {qb.x, qb.y}, oB[2] = {qb.z, qb.w};
#pragma unroll
    for (int i = 0; i < 2; ++i) {
#pragma unroll
        for (int j = 0; j < 2; ++j) {
            const ulonglong2 W = *reinterpret_cast<const ulonglong2*>(w + (i * 2 + j) * 4);
            ull pA = bcast2(eA[i] * oA[j]);
            ull pB = bcast2(eB[i] * oB[j]);
            cA0 = ffma2(pA, W.x, cA0);  cA1 = ffma2(pA, W.y, cA1);
            cB0 = ffma2(pB, W.x, cB0);  cB1 = ffma2(pB, W.y, cB1);
        }
    }
    unpack2(cA0, hA[0], hA[1]);  unpack2(cA1, hA[2], hA[3]);
    unpack2(cB0, hB[0], hB[1]);  unpack2(cB1, hB[2], hB[3]);
}

// 4x4->8, two samples sharing W (128 floats)
__device__ __forceinline__ void contract448_2(const float* aA, const float* bA,
                                              const float* aB, const float* bB,
                                              const float* __restrict__ w,
                                              float* outA, float* outB) {
    ull cA[4] = {0, 0, 0, 0}, cB[4] = {0, 0, 0, 0};
#pragma unroll
    for (int i = 0; i < 4; ++i) {
        ull tA[4] = {0, 0, 0, 0}, tB[4] = {0, 0, 0, 0};
#pragma unroll
        for (int j = 0; j < 4; ++j) {
            const ulonglong2* wp = reinterpret_cast<const ulonglong2*>(w + (i * 4 + j) * 8);
            ulonglong2 W01 = wp[0];
            ulonglong2 W23 = wp[1];
            ull bb = bcast2(bA[j]);
            tA[0] = ffma2(bb, W01.x, tA[0]);  tA[1] = ffma2(bb, W01.y, tA[1]);
            tA[2] = ffma2(bb, W23.x, tA[2]);  tA[3] = ffma2(bb, W23.y, tA[3]);
            bb = bcast2(bB[j]);
            tB[0] = ffma2(bb, W01.x, tB[0]);  tB[1] = ffma2(bb, W01.y, tB[1]);
            tB[2] = ffma2(bb, W23.x, tB[2]);  tB[3] = ffma2(bb, W23.y, tB[3]);
        }
        ull ai = bcast2(aA[i]);
        cA[0] = ffma2(ai, tA[0], cA[0]);  cA[1] = ffma2(ai, tA[1], cA[1]);
        cA[2] = ffma2(ai, tA[2], cA[2]);  cA[3] = ffma2(ai, tA[3], cA[3]);
        ai = bcast2(aB[i]);
        cB[0] = ffma2(ai, tB[0], cB[0]);  cB[1] = ffma2(ai, tB[1], cB[1]);
        cB[2] = ffma2(ai, tB[2], cB[2]);  cB[3] = ffma2(ai, tB[3], cB[3]);
    }
    unpack2(cA[0], outA[0], outA[1]);  unpack2(cA[1], outA[2], outA[3]);
    unpack2(cA[2], outA[4], outA[5]);  unpack2(cA[3], outA[6], outA[7]);
    unpack2(cB[0], outB[0], outB[1]);  unpack2(cB[1], outB[2], outB[3]);
    unpack2(cB[2], outB[4], outB[5]);  unpack2(cB[3], outB[6], outB[7]);
}

// 8x8->8, two samples sharing W (512 floats), software-pipelined weight loads.
// out may alias b.
__device__ __forceinline__ void contract888_2(const float* aA, const float* bA,
                                              const float* aB, const float* bB,
                                              const float* __restrict__ w,
                                              float* outA, float* outB) {
    const ulonglong2* wp = reinterpret_cast<const ulonglong2*>(w);
    ull cA[4] = {0, 0, 0, 0}, cB[4] = {0, 0, 0, 0};
    ulonglong2 W01 = wp[0];
    ulonglong2 W23 = wp[1];
#pragma unroll
    for (int i = 0; i < 8; ++i) {
        ull tA[4] = {0, 0, 0, 0}, tB[4] = {0, 0, 0, 0};
#pragma unroll
        for (int j = 0; j < 8; ++j) {
            const int nidx = i * 8 + j + 1;
            ulonglong2 nW01, nW23;
            if (nidx < 64) {
                nW01 = wp[2 * nidx];
                nW23 = wp[2 * nidx + 1];
            }
            ull bb = bcast2(bA[j]);
            tA[0] = ffma2(bb, W01.x, tA[0]);  tA[1] = ffma2(bb, W01.y, tA[1]);
            tA[2] = ffma2(bb, W23.x, tA[2]);  tA[3] = ffma2(bb, W23.y, tA[3]);
            bb = bcast2(bB[j]);
            tB[0] = ffma2(bb, W01.x, tB[0]);  tB[1] = ffma2(bb, W01.y, tB[1]);
            tB[2] = ffma2(bb, W23.x, tB[2]);  tB[3] = ffma2(bb, W23.y, tB[3]);
            if (nidx < 64) { W01 = nW01; W23 = nW23; }
        }
        ull ai = bcast2(aA[i]);
        cA[0] = ffma2(ai, tA[0], cA[0]);  cA[1] = ffma2(ai, tA[1], cA[1]);
        cA[2] = ffma2(ai, tA[2], cA[2]);  cA[3] = ffma2(ai, tA[3], cA[3]);
        ai = bcast2(aB[i]);
        cB[0] = ffma2(ai, tB[0], cB[0]);  cB[1] = ffma2(ai, tB[1], cB[1]);
        cB[2] = ffma2(ai, tB[2], cB[2]);  cB[3] = ffma2(ai, tB[3], cB[3]);
    }
    unpack2(cA[0], outA[0], outA[1]);  unpack2(cA[1], outA[2], outA[3]);
    unpack2(cA[2], outA[4], outA[5]);  unpack2(cA[3], outA[6], outA[7]);
    unpack2(cB[0], outB[0], outB[1]);  unpack2(cB[1], outB[2], outB[3]);
    unpack2(cB[2], outB[4], outB[5]);  unpack2(cB[3], outB[6], outB[7]);
}

// 8x8->8 single sample (merge kernel)
__device__ __forceinline__ void contract888_1(const float* a, const float* b,
                                              const float* __restrict__ w, float* out) {
    ull c[4] = {0, 0, 0, 0};
#pragma unroll
    for (int i = 0; i < 8; ++i) {
        ull t[4] = {0, 0, 0, 0};
        const float* base = w + i * 64;
#pragma unroll
        for (int j = 0; j < 8; ++j) {
            const ulonglong2* wp = reinterpret_cast<const ulonglong2*>(base + j * 8);
            ulonglong2 W01 = wp[0];
            ulonglong2 W23 = wp[1];
            ull bb = bcast2(b[j]);
            t[0] = ffma2(bb, W01.x, t[0]);  t[1] = ffma2(bb, W01.y, t[1]);
            t[2] = ffma2(bb, W23.x, t[2]);  t[3] = ffma2(bb, W23.y, t[3]);
        }
        ull ai = bcast2(a[i]);
        c[0] = ffma2(ai, t[0], c[0]);  c[1] = ffma2(ai, t[1], c[1]);
        c[2] = ffma2(ai, t[2], c[2]);  c[3] = ffma2(ai, t[3], c[3]);
    }
    unpack2(c[0], out[0], out[1]);  unpack2(c[1], out[2], out[3]);
    unpack2(c[2], out[4], out[5]);  unpack2(c[3], out[6], out[7]);
}

__device__ __forceinline__ void scopy4(float* dst, const float* __restrict__ src, int n4) {
    const float4* s = reinterpret_cast<const float4*>(src);
    float4* d = reinterpret_cast<float4*>(dst);
    for (int i = threadIdx.x; i < n4; i += blockDim.x) d[i] = s[i];
}

__device__ __forceinline__ void store_pair(float4* buf, int b, const float* v) {
    buf[(size_t)b * 2 + 0] = make_float4(v[0], v[1], v[2], v[3]);
    buf[(size_t)b * 2 + 1] = make_float4(v[4], v[5], v[6], v[7]);
}

__global__ void __launch_bounds__(T1, 8)
tn_eighth_kernel(const float* __restrict__ x,
                 const float* __restrict__ w7, const float* __restrict__ w6,
                 const float* __restrict__ w5, const float* __restrict__ w4,
                 const float* __restrict__ w3) {
    extern __shared__ float sw[];

    const int e   = blockIdx.x >> 9;      // eighth 0..7
    const int blk = blockIdx.x & 511;

    scopy4(sw + E7, w7 + e * 256,   256 / 4);
    scopy4(sw + E6, w6 + e * 1024, 1024 / 4);
    scopy4(sw + E5, w5 + e * 2048, 2048 / 4);
    scopy4(sw + E4, w4 + e * 1024, 1024 / 4);
    scopy4(sw + E3, w3 + e * 512,   512 / 4);
    __syncthreads();

    const int bA = blk * T1 + threadIdx.x;
    const int bB = bA + HALF;
    const float4* xA = reinterpret_cast<const float4*>(x) + (size_t)bA * 128 + e * 16;
    const float4* xB = reinterpret_cast<const float4*>(x) + (size_t)bB * 128 + e * 16;

    float stkA0[8], stkA1[8], stkA2[8];
    float stkB0[8], stkB1[8], stkB2[8];

#pragma unroll 1
    for (int m = 0; m < 8; ++m) {
        float4 qA0 = __ldg(xA + 2 * m);
        float4 qA1 = __ldg(xA + 2 * m + 1);
        float4 qB0 = __ldg(xB + 2 * m);
        float4 qB1 = __ldg(xB + 2 * m + 1);

        float laA[4], lbA[4], laB[4], lbB[4];
        leaf2(qA0, qB0, sw + E7 + (2 * m) * 16, laA, laB);
        leaf2(qA1, qB1, sw + E7 + (2 * m + 1) * 16, lbA, lbB);

        float curA[8], curB[8];
        contract448_2(laA, lbA, laB, lbB, sw + E6 + m * 128, curA, curB);

        if (!(m & 1)) {
            cp8(stkA0, curA);  cp8(stkB0, curB);
        } else {
            contract888_2(stkA0, curA, stkB0, curB, sw + E5 + (m >> 1) * 512, curA, curB);
            if (!((m >> 1) & 1)) {
                cp8(stkA1, curA);  cp8(stkB1, curB);
            } else {
                contract888_2(stkA1, curA, stkB1, curB, sw + E4 + (m >> 2) * 512, curA, curB);
                if (!((m >> 2) & 1)) {
                    cp8(stkA2, curA);  cp8(stkB2, curB);
                } else {
                    // m == 7: top of this eighth (w3 node)
                    contract888_2(stkA2, curA, stkB2, curB, sw + E3, curA, curB);
                    float4* eb = g_ebuf + ((size_t)e * NB) * 2;
                    store_pair(eb, bA, curA);
                    store_pair(eb, bB, curB);
                }
            }
        }
    }
}

// merge: w2 (4 nodes), w1 (2 nodes), w0 root; 1 sample/thread.
// All 16 global loads issued upfront (MLP=16) to cover DRAM latency.
__global__ void __launch_bounds__(T2)
tn_merge_kernel(const float* __restrict__ w2, const float* __restrict__ w1,
                const float* __restrict__ w0, float* __restrict__ out) {
    __shared__ float w2s[2048];
    __shared__ float w1s[1024];
    __shared__ float w0s[128];
    scopy4(w2s, w2, 2048 / 4);
    scopy4(w1s, w1, 1024 / 4);
    scopy4(w0s, w0, 128 / 4);

    const int b = blockIdx.x * T2 + threadIdx.x;

    // hoist all 16 loads (independent -> high MLP)
    float4 p[16];
#pragma unroll
    for (int e = 0; e < 8; ++e) {
        p[2 * e + 0] = __ldg(g_ebuf + ((size_t)e * NB + b) * 2 + 0);
        p[2 * e + 1] = __ldg(g_ebuf + ((size_t)e * NB + b) * 2 + 1);
    }
    __syncthreads();

    float v[8][8];
#pragma unroll
    for (int e = 0; e < 8; ++e) {
        v[e][0] = p[2 * e].x;     v[e][1] = p[2 * e].y;
        v[e][2] = p[2 * e].z;     v[e][3] = p[2 * e].w;
        v[e][4] = p[2 * e + 1].x; v[e][5] = p[2 * e + 1].y;
        v[e][6] = p[2 * e + 1].z; v[e][7] = p[2 * e + 1].w;
    }

    float hL[8], hR[8], q0[8], q1[8];
    contract888_1(v[0], v[1], w2s, q0);
    contract888_1(v[2], v[3], w2s + 512, q1);
    contract888_1(q0, q1, w1s, hL);
    contract888_1(v[4], v[5], w2s + 1024, q0);
    contract888_1(v[6], v[7], w2s + 1536, q1);
    contract888_1(q0, q1, w1s + 512, hR);

    ull acc = 0ull;
#pragma unroll
    for (int i = 0; i < 8; ++i) {
        ull ai = bcast2(hL[i]);
#pragma unroll
        for (int j = 0; j < 8; ++j) {
            ull W = *reinterpret_cast<const ull*>(w0s + (i * 8 + j) * 2);
            acc = ffma2(ffma2(ai, bcast2(hR[j]), 0ull), W, acc);
        }
    }
    float r0, r1;
    unpack2(acc, r0, r1);
    reinterpret_cast<float2*>(out)[b] = make_float2(r0, r1);
}

extern "C" void kernel_launch(void* const* d_in, const int* in_sizes, int n_in,
                              void* d_out, int out_size) {
    const float* x  = (const float*)d_in[0];
    const float* w7 = (const float*)d_in[1];
    const float* w6 = (const float*)d_in[2];
    const float* w5 = (const float*)d_in[3];
    const float* w4 = (const float*)d_in[4];
    const float* w3 = (const float*)d_in[5];
    const float* w2 = (const float*)d_in[6];
    const float* w1 = (const float*)d_in[7];
    const float* w0 = (const float*)d_in[8];
    float* out = (float*)d_out;

    const size_t smem = SMEM1_FLOATS * sizeof(float);
    cudaFuncSetAttribute(tn_eighth_kernel, cudaFuncAttributeMaxDynamicSharedMemorySize, (int)smem);
    tn_eighth_kernel<<<NBLOCKS1, T1, smem>>>(x, w7, w6, w5, w4, w3);
    tn_merge_kernel<<<NBLOCKS2, T2>>>(w2, w1, w0, out);
}

// round 10
// speedup vs baseline: 1.0233x; 1.0233x over previous
#include <cuda_runtime.h>

// ---------------------------------------------------------------------------
// TNModel binary-tree TN, B=65536. Round 10: two kernels (fusion abandoned).
// Kernel 1 (unchanged from R7): eighth subtree (w7..w3) per CTA, T1=64,
// 8 CTAs/SM, 2 samples/thread, weight-prefetch pipeline.
// Kernel 2 (redesigned): 2 samples x ONE side per thread -> chain depth 3
// (w2,w2,w1) + root; sides per-warp (uniform weights); hL/hR exchanged via
// padded smem. 2x warps, ~half the dependent latency of the old merge.
// ---------------------------------------------------------------------------

#define NB       65536
#define HALF     (NB / 2)            // 32768
#define T1       64                  // threads, kernel 1
#define BLK_E    (HALF / T1)         // 512 blocks per eighth
#define NBLOCKS1 (8 * BLK_E)         // 4096
#define T2       128                 // threads, kernel 2
#define NBLOCKS2 512                 // 64 sample-pairs per block

// eighth-tree shared-memory float offsets
#define E7 0                      // 16 x 16   =  256
#define E6 (E7 + 256)             //  8 x 128  = 1024
#define E5 (E6 + 1024)            //  4 x 512  = 2048
#define E4 (E5 + 2048)            //  2 x 512  = 1024
#define E3 (E4 + 1024)            //  1 x 512  =  512
#define SMEM1_FLOATS (E3 + 512)   // 4864 floats = 19456 bytes

typedef unsigned long long ull;

__device__ float4 g_ebuf[8 * NB * 2];   // [eighth][sample][2 x float4]

__device__ __forceinline__ ull ffma2(ull a, ull b, ull c) {
    ull d;
    asm("fma.rn.f32x2 %0, %1, %2, %3;" : "=l"(d) : "l"(a), "l"(b), "l"(c));
    return d;
}
__device__ __forceinline__ ull bcast2(float x) {
    ull r;
    asm("mov.b64 %0, {%1, %1};" : "=l"(r) : "f"(x));
    return r;
}
__device__ __forceinline__ void unpack2(ull v, float& lo, float& hi) {
    asm("mov.b64 {%0, %1}, %2;" : "=f"(lo), "=f"(hi) : "l"(v));
}
__device__ __forceinline__ void cp8(float* d, const float* s) {
#pragma unroll
    for (int k = 0; k < 8; ++k) d[k] = s[k];
}

// leaf for two samples sharing W (16 floats)
__device__ __forceinline__ void leaf2(float4 qa, float4 qb,
                                      const float* __restrict__ w,
                                      float* hA, float* hB) {
    ull cA0 = 0, cA1 = 0, cB0 = 0, cB1 = 0;
    float eA[2] = {qa.x, qa.y}, oA[2] = {qa.z, qa.w};
    float eB[2] = {qb.x, qb.y}, oB[2] = {qb.z, qb.w};
#pragma unroll
    for (int i = 0; i < 2; ++i) {
#pragma unroll
        for (int j = 0; j < 2; ++j) {
            const ulonglong2 W = *reinterpret_cast<const ulonglong2*>(w + (i * 2 + j) * 4);
            ull pA = bcast2(eA[i] * oA[j]);
            ull pB = bcast2(eB[i] * oB[j]);
            cA0 = ffma2(pA, W.x, cA0);  cA1 = ffma2(pA, W.y, cA1);
            cB0 = ffma2(pB, W.x, cB0);  cB1 = ffma2(pB, W.y, cB1);
        }
    }
    unpack2(cA0, hA[0], hA[1]);  unpack2(cA1, hA[2], hA[3]);
    unpack2(cB0, hB[0], hB[1]);  unpack2(cB1, hB[2], hB[3]);
}

// 4x4->8, two samples sharing W (128 floats, smem)
__device__ __forceinline__ void contract448_2(const float* aA, const float* bA,
                                              const float* aB, const float* bB,
                                              const float* __restrict__ w,
                                              float* outA, float* outB) {
    ull cA[4] = {0, 0, 0, 0}, cB[4] = {0, 0, 0, 0};
#pragma unroll
    for (int i = 0; i < 4; ++i) {
        ull tA[4] = {0, 0, 0, 0}, tB[4] = {0, 0, 0, 0};
#pragma unroll
        for (int j = 0; j < 4; ++j) {
            const ulonglong2* wp = reinterpret_cast<const ulonglong2*>(w + (i * 4 + j) * 8);
            ulonglong2 W01 = wp[0];
            ulonglong2 W23 = wp[1];
            ull bb = bcast2(bA[j]);
            tA[0] = ffma2(bb, W01.x, tA[0]);  tA[1] = ffma2(bb, W01.y, tA[1]);
            tA[2] = ffma2(bb, W23.x, tA[2]);  tA[3] = ffma2(bb, W23.y, tA[3]);
            bb = bcast2(bB[j]);
            tB[0] = ffma2(bb, W01.x, tB[0]);  tB[1] = ffma2(bb, W01.y, tB[1]);
            tB[2] = ffma2(bb, W23.x, tB[2]);  tB[3] = ffma2(bb, W23.y, tB[3]);
        }
        ull ai = bcast2(aA[i]);
        cA[0] = ffma2(ai, tA[0], cA[0]);  cA[1] = ffma2(ai, tA[1], cA[1]);
        cA[2] = ffma2(ai, tA[2], cA[2]);  cA[3] = ffma2(ai, tA[3], cA[3]);
        ai = bcast2(aB[i]);
        cB[0] = ffma2(ai, tB[0], cB[0]);  cB[1] = ffma2(ai, tB[1], cB[1]);
        cB[2] = ffma2(ai, tB[2], cB[2]);  cB[3] = ffma2(ai, tB[3], cB[3]);
    }
    unpack2(cA[0], outA[0], outA[1]);  unpack2(cA[1], outA[2], outA[3]);
    unpack2(cA[2], outA[4], outA[5]);  unpack2(cA[3], outA[6], outA[7]);
    unpack2(cB[0], outB[0], outB[1]);  unpack2(cB[1], outB[2], outB[3]);
    unpack2(cB[2], outB[4], outB[5]);  unpack2(cB[3], outB[6], outB[7]);
}

// 8x8->8, two samples sharing W (512 floats, smem), software-pipelined. out may alias b.
__device__ __forceinline__ void contract888_2(const float* aA, const float* bA,
                                              const float* aB, const float* bB,
                                              const float* __restrict__ w,
                                              float* outA, float* outB) {
    const ulonglong2* wp = reinterpret_cast<const ulonglong2*>(w);
    ull cA[4] = {0, 0, 0, 0}, cB[4] = {0, 0, 0, 0};
    ulonglong2 W01 = wp[0];
    ulonglong2 W23 = wp[1];
#pragma unroll
    for (int i = 0; i < 8; ++i) {
        ull tA[4] = {0, 0, 0, 0}, tB[4] = {0, 0, 0, 0};
#pragma unroll
        for (int j = 0; j < 8; ++j) {
            const int nidx = i * 8 + j + 1;
            ulonglong2 nW01, nW23;
            if (nidx < 64) {
                nW01 = wp[2 * nidx];
                nW23 = wp[2 * nidx + 1];
            }
            ull bb = bcast2(bA[j]);
            tA[0] = ffma2(bb, W01.x, tA[0]);  tA[1] = ffma2(bb, W01.y, tA[1]);
            tA[2] = ffma2(bb, W23.x, tA[2]);  tA[3] = ffma2(bb, W23.y, tA[3]);
            bb = bcast2(bB[j]);
            tB[0] = ffma2(bb, W01.x, tB[0]);  tB[1] = ffma2(bb, W01.y, tB[1]);
            tB[2] = ffma2(bb, W23.x, tB[2]);  tB[3] = ffma2(bb, W23.y, tB[3]);
            if (nidx < 64) { W01 = nW01; W23 = nW23; }
        }
        ull ai = bcast2(aA[i]);
        cA[0] = ffma2(ai, tA[0], cA[0]);  cA[1] = ffma2(ai, tA[1], cA[1]);
        cA[2] = ffma2(ai, tA[2], cA[2]);  cA[3] = ffma2(ai, tA[3], cA[3]);
        ai = bcast2(aB[i]);
        cB[0] = ffma2(ai, tB[0], cB[0]);  cB[1] = ffma2(ai, tB[1], cB[1]);
        cB[2] = ffma2(ai, tB[2], cB[2]);  cB[3] = ffma2(ai, tB[3], cB[3]);
    }
    unpack2(cA[0], outA[0], outA[1]);  unpack2(cA[1], outA[2], outA[3]);
    unpack2(cA[2], outA[4], outA[5]);  unpack2(cA[3], outA[6], outA[7]);
    unpack2(cB[0], outB[0], outB[1]);  unpack2(cB[1], outB[2], outB[3]);
    unpack2(cB[2], outB[4], outB[5]);  unpack2(cB[3], outB[6], outB[7]);
}

__device__ __forceinline__ void scopy4(float* dst, const float* __restrict__ src, int n4) {
    const float4* s = reinterpret_cast<const float4*>(src);
    float4* d = reinterpret_cast<float4*>(dst);
    for (int i = threadIdx.x; i < n4; i += blockDim.x) d[i] = s[i];
}

__device__ __forceinline__ void store_pair(float4* buf, int b, const float* v) {
    buf[(size_t)b * 2 + 0] = make_float4(v[0], v[1], v[2], v[3]);
    buf[(size_t)b * 2 + 1] = make_float4(v[4], v[5], v[6], v[7]);
}
__device__ __forceinline__ void load_pair(int e, int b, float* v) {
    float4 p0 = __ldg(g_ebuf + ((size_t)e * NB + b) * 2 + 0);
    float4 p1 = __ldg(g_ebuf + ((size_t)e * NB + b) * 2 + 1);
    v[0] = p0.x; v[1] = p0.y; v[2] = p0.z; v[3] = p0.w;
    v[4] = p1.x; v[5] = p1.y; v[6] = p1.z; v[7] = p1.w;
}

// ------------------------------- kernel 1 ----------------------------------
__global__ void __launch_bounds__(T1, 8)
tn_eighth_kernel(const float* __restrict__ x,
                 const float* __restrict__ w7, const float* __restrict__ w6,
                 const float* __restrict__ w5, const float* __restrict__ w4,
                 const float* __restrict__ w3) {
    extern __shared__ float sw[];

    const int e   = blockIdx.x >> 9;      // eighth 0..7
    const int blk = blockIdx.x & 511;

    scopy4(sw + E7, w7 + e * 256,   256 / 4);
    scopy4(sw + E6, w6 + e * 1024, 1024 / 4);
    scopy4(sw + E5, w5 + e * 2048, 2048 / 4);
    scopy4(sw + E4, w4 + e * 1024, 1024 / 4);
    scopy4(sw + E3, w3 + e * 512,   512 / 4);
    __syncthreads();

    const int bA = blk * T1 + threadIdx.x;
    const int bB = bA + HALF;
    const float4* xA = reinterpret_cast<const float4*>(x) + (size_t)bA * 128 + e * 16;
    const float4* xB = reinterpret_cast<const float4*>(x) + (size_t)bB * 128 + e * 16;

    float stkA0[8], stkA1[8], stkA2[8];
    float stkB0[8], stkB1[8], stkB2[8];

#pragma unroll 1
    for (int m = 0; m < 8; ++m) {
        float4 qA0 = __ldg(xA + 2 * m);
        float4 qA1 = __ldg(xA + 2 * m + 1);
        float4 qB0 = __ldg(xB + 2 * m);
        float4 qB1 = __ldg(xB + 2 * m + 1);

        float laA[4], lbA[4], laB[4], lbB[4];
        leaf2(qA0, qB0, sw + E7 + (2 * m) * 16, laA, laB);
        leaf2(qA1, qB1, sw + E7 + (2 * m + 1) * 16, lbA, lbB);

        float curA[8], curB[8];
        contract448_2(laA, lbA, laB, lbB, sw + E6 + m * 128, curA, curB);

        if (!(m & 1)) {
            cp8(stkA0, curA);  cp8(stkB0, curB);
        } else {
            contract888_2(stkA0, curA, stkB0, curB, sw + E5 + (m >> 1) * 512, curA, curB);
            if (!((m >> 1) & 1)) {
                cp8(stkA1, curA);  cp8(stkB1, curB);
            } else {
                contract888_2(stkA1, curA, stkB1, curB, sw + E4 + (m >> 2) * 512, curA, curB);
                if (!((m >> 2) & 1)) {
                    cp8(stkA2, curA);  cp8(stkB2, curB);
                } else {
                    // m == 7: top of this eighth (w3 node)
                    contract888_2(stkA2, curA, stkB2, curB, sw + E3, curA, curB);
                    float4* eb = g_ebuf + ((size_t)e * NB) * 2;
                    store_pair(eb, bA, curA);
                    store_pair(eb, bB, curB);
                }
            }
        }
    }
}

// ------------------------------- kernel 2 ----------------------------------
// Each thread: 2 samples (bA, bB=bA+HALF) x ONE side (left/right half-tree).
// Warp-uniform side -> uniform weight addresses. Chain: w2, w2, w1, then root
// after a smem exchange of the opposite half's vector.
__global__ void __launch_bounds__(T2)
tn_merge_kernel(const float* __restrict__ w2, const float* __restrict__ w1,
                const float* __restrict__ w0, float* __restrict__ out) {
    __shared__ float w2s[2048];
    __shared__ float w1s[1024];
    __shared__ float w0s[128];
    __shared__ float xchA[2][32 * 9];   // hR of sample A (written by side-1 warp)
    __shared__ float xchB[2][32 * 9];   // hL of sample B (written by side-0 warp)

    scopy4(w2s, w2, 2048 / 4);
    scopy4(w1s, w1, 1024 / 4);
    scopy4(w0s, w0, 128 / 4);
    __syncthreads();

    const int warp  = threadIdx.x >> 5;
    const int lane  = threadIdx.x & 31;
    const int side  = warp & 1;         // 0: left (eighths 0..3), 1: right (4..7)
    const int pairi = warp >> 1;        // which 32-sample group in this block
    const int bA = blockIdx.x * 64 + pairi * 32 + lane;
    const int bB = bA + HALF;
    const int eb = side * 4;

    float vA0[8], vA1[8], vB0[8], vB1[8];
    float qA0[8], qB0[8], hA[8], hB[8];

    // first w2 node of this side
    load_pair(eb + 0, bA, vA0);
    load_pair(eb + 1, bA, vA1);
    load_pair(eb + 0, bB, vB0);
    load_pair(eb + 1, bB, vB1);
    contract888_2(vA0, vA1, vB0, vB1, w2s + (2 * side) * 512, qA0, qB0);

    // second w2 node of this side
    load_pair(eb + 2, bA, vA0);
    load_pair(eb + 3, bA, vA1);
    load_pair(eb + 2, bB, vB0);
    load_pair(eb + 3, bB, vB1);
    contract888_2(vA0, vA1, vB0, vB1, w2s + (2 * side + 1) * 512, vA0, vB0);

    // w1 node of this side -> h (this side's half-tree vector)
    contract888_2(qA0, vA0, qB0, vB0, w1s + side * 512, hA, hB);

    // exchange: side-1 publishes hA (=hR of sample A); side-0 publishes hB (=hL of sample B)
    if (side) {
#pragma unroll
        for (int k = 0; k < 8; ++k) xchA[pairi][lane * 9 + k] = hA[k];
    } else {
#pragma unroll
        for (int k = 0; k < 8; ++k) xchB[pairi][lane * 9 + k] = hB[k];
    }
    __syncthreads();

    // roots: side-0 warp computes sample A, side-1 warp computes sample B
    float hL[8], hR[8];
    int bo;
    if (side == 0) {
#pragma unroll
        for (int k = 0; k < 8; ++k) { hL[k] = hA[k]; hR[k] = xchA[pairi][lane * 9 + k]; }
        bo = bA;
    } else {
#pragma unroll
        for (int k = 0; k < 8; ++k) { hL[k] = xchB[pairi][lane * 9 + k]; hR[k] = hB[k]; }
        bo = bB;
    }

    ull acc = 0ull;
#pragma unroll
    for (int i = 0; i < 8; ++i) {
        ull ai = bcast2(hL[i]);
#pragma unroll
        for (int j = 0; j < 8; ++j) {
            ull W = *reinterpret_cast<const ull*>(w0s + (i * 8 + j) * 2);
            acc = ffma2(ffma2(ai, bcast2(hR[j]), 0ull), W, acc);
        }
    }
    float r0, r1;
    unpack2(acc, r0, r1);
    reinterpret_cast<float2*>(out)[bo] = make_float2(r0, r1);
}

extern "C" void kernel_launch(void* const* d_in, const int* in_sizes, int n_in,
                              void* d_out, int out_size) {
    const float* x  = (const float*)d_in[0];
    const float* w7 = (const float*)d_in[1];
    const float* w6 = (const float*)d_in[2];
    const float* w5 = (const float*)d_in[3];
    const float* w4 = (const float*)d_in[4];
    const float* w3 = (const float*)d_in[5];
    const float* w2 = (const float*)d_in[6];
    const float* w1 = (const float*)d_in[7];
    const float* w0 = (const float*)d_in[8];
    float* out = (float*)d_out;

    const size_t smem = SMEM1_FLOATS * sizeof(float);
    cudaFuncSetAttribute(tn_eighth_kernel, cudaFuncAttributeMaxDynamicSharedMemorySize, (int)smem);
    tn_eighth_kernel<<<NBLOCKS1, T1, smem>>>(x, w7, w6, w5, w4, w3);
    tn_merge_kernel<<<NBLOCKS2, T2>>>(w2, w1, w0, out);
}

// round 11
// speedup vs baseline: 1.0253x; 1.0019x over previous
#include <cuda_runtime.h>

// ---------------------------------------------------------------------------
// TNModel binary-tree TN, B=65536. Round 11:
// Kernel 1: eighth subtree per CTA (T1=64, 8 CTAs/SM, 2 samples/thread,
//   weight-prefetch pipeline) + hoisted sample-A b-broadcasts in the 8x8x8
//   contraction (fewer ALU MOV issue slots).
// Kernel 2: side-split merge, T2=64 / grid 1024 -> one full wave, no tail.
// ---------------------------------------------------------------------------

#define NB       65536
#define HALF     (NB / 2)            // 32768
#define T1       64                  // threads, kernel 1
#define BLK_E    (HALF / T1)         // 512 blocks per eighth
#define NBLOCKS1 (8 * BLK_E)         // 4096
#define T2       64                  // threads, kernel 2
#define NBLOCKS2 (HALF / 32)         // 1024 (32 sample-pairs per block)

// eighth-tree shared-memory float offsets
#define E7 0                      // 16 x 16   =  256
#define E6 (E7 + 256)             //  8 x 128  = 1024
#define E5 (E6 + 1024)            //  4 x 512  = 2048
#define E4 (E5 + 2048)            //  2 x 512  = 1024
#define E3 (E4 + 1024)            //  1 x 512  =  512
#define SMEM1_FLOATS (E3 + 512)   // 4864 floats = 19456 bytes

typedef unsigned long long ull;

__device__ float4 g_ebuf[8 * NB * 2];   // [eighth][sample][2 x float4]

__device__ __forceinline__ ull ffma2(ull a, ull b, ull c) {
    ull d;
    asm("fma.rn.f32x2 %0, %1, %2, %3;" : "=l"(d) : "l"(a), "l"(b), "l"(c));
    return d;
}
__device__ __forceinline__ ull bcast2(float x) {
    ull r;
    asm("mov.b64 %0, {%1, %1};" : "=l"(r) : "f"(x));
    return r;
}
__device__ __forceinline__ void unpack2(ull v, float& lo, float& hi) {
    asm("mov.b64 {%0, %1}, %2;" : "=f"(lo), "=f"(hi) : "l"(v));
}
__device__ __forceinline__ void cp8(float* d, const float* s) {
#pragma unroll
    for (int k = 0; k < 8; ++k) d[k] = s[k];
}

// leaf for two samples sharing W (16 floats)
__device__ __forceinline__ void leaf2(float4 qa, float4 qb,
                                      const float* __restrict__ w,
                                      float* hA, float* hB) {
    ull cA0 = 0, cA1 = 0, cB0 = 0, cB1 = 0;
    float eA[2] = {qa.x, qa.y}, oA[2] = {qa.z, qa.w};
    float eB[2] = {qb.x, qb.y}, oB[2] = {qb.z, qb.w};
#pragma unroll
    for (int i = 0; i < 2; ++i) {
#pragma unroll
        for (int j = 0; j < 2; ++j) {
            const ulonglong2 W = *reinterpret_cast<const ulonglong2*>(w + (i * 2 + j) * 4);
            ull pA = bcast2(eA[i] * oA[j]);
            ull pB = bcast2(eB[i] * oB[j]);
            cA0 = ffma2(pA, W.x, cA0);  cA1 = ffma2(pA, W.y, cA1);
            cB0 = ffma2(pB, W.x, cB0);  cB1 = ffma2(pB, W.y, cB1);
        }
    }
    unpack2(cA0, hA[0], hA[1]);  unpack2(cA1, hA[2], hA[3]);
    unpack2(cB0, hB[0], hB[1]);  unpack2(cB1, hB[2], hB[3]);
}

// 4x4->8, two samples sharing W (128 floats, smem)
__device__ __forceinline__ void contract448_2(const float* aA, const float* bA,
                                              const float* aB, const float* bB,
                                              const float* __restrict__ w,
                                              float* outA, float* outB) {
    ull cA[4] = {0, 0, 0, 0}, cB[4] = {0, 0, 0, 0};
#pragma unroll
    for (int i = 0; i < 4; ++i) {
        ull tA[4] = {0, 0, 0, 0}, tB[4] = {0, 0, 0, 0};
#pragma unroll
        for (int j = 0; j < 4; ++j) {
            const ulonglong2* wp = reinterpret_cast<const ulonglong2*>(w + (i * 4 + j) * 8);
            ulonglong2 W01 = wp[0];
            ulonglong2 W23 = wp[1];
            ull bb = bcast2(bA[j]);
            tA[0] = ffma2(bb, W01.x, tA[0]);  tA[1] = ffma2(bb, W01.y, tA[1]);
            tA[2] = ffma2(bb, W23.x, tA[2]);  tA[3] = ffma2(bb, W23.y, tA[3]);
            bb = bcast2(bB[j]);
            tB[0] = ffma2(bb, W01.x, tB[0]);  tB[1] = ffma2(bb, W01.y, tB[1]);
            tB[2] = ffma2(bb, W23.x, tB[2]);  tB[3] = ffma2(bb, W23.y, tB[3]);
        }
        ull ai = bcast2(aA[i]);
        cA[0] = ffma2(ai, tA[0], cA[0]);  cA[1] = ffma2(ai, tA[1], cA[1]);
        cA[2] = ffma2(ai, tA[2], cA[2]);  cA[3] = ffma2(ai, tA[3], cA[3]);
        ai = bcast2(aB[i]);
        cB[0] = ffma2(ai, tB[0], cB[0]);  cB[1] = ffma2(ai, tB[1], cB[1]);
        cB[2] = ffma2(ai, tB[2], cB[2]);  cB[3] = ffma2(ai, tB[3], cB[3]);
    }
    unpack2(cA[0], outA[0], outA[1]);  unpack2(cA[1], outA[2], outA[3]);
    unpack2(cA[2], outA[4], outA[5]);  unpack2(cA[3], outA[6], outA[7]);
    unpack2(cB[0], outB[0], outB[1]);  unpack2(cB[1], outB[2], outB[3]);
    unpack2(cB[2], outB[4], outB[5]);  unpack2(cB[3], outB[6], outB[7]);
}

// 8x8->8, two samples sharing W (512 floats, smem), software-pipelined weight
// loads, sample-A b-broadcasts hoisted to node scope. out may alias b.
__device__ __forceinline__ void contract888_2(const float* aA, const float* bA,
                                              const float* aB, const float* bB,
                                              const float* __restrict__ w,
                                              float* outA, float* outB) {
    const ulonglong2* wp = reinterpret_cast<const ulonglong2*>(w);
    ull cA[4] = {0, 0, 0, 0}, cB[4] = {0, 0, 0, 0};
    ull bbA[8];
#pragma unroll
    for (int j = 0; j < 8; ++j) bbA[j] = bcast2(bA[j]);
    ulonglong2 W01 = wp[0];
    ulonglong2 W23 = wp[1];
#pragma unroll
    for (int i = 0; i < 8; ++i) {
        ull tA[4] = {0, 0, 0, 0}, tB[4] = {0, 0, 0, 0};
#pragma unroll
        for (int j = 0; j < 8; ++j) {
            const int nidx = i * 8 + j + 1;
            ulonglong2 nW01, nW23;
            if (nidx < 64) {
                nW01 = wp[2 * nidx];
                nW23 = wp[2 * nidx + 1];
            }
            tA[0] = ffma2(bbA[j], W01.x, tA[0]);  tA[1] = ffma2(bbA[j], W01.y, tA[1]);
            tA[2] = ffma2(bbA[j], W23.x, tA[2]);  tA[3] = ffma2(bbA[j], W23.y, tA[3]);
            ull bb = bcast2(bB[j]);
            tB[0] = ffma2(bb, W01.x, tB[0]);  tB[1] = ffma2(bb, W01.y, tB[1]);
            tB[2] = ffma2(bb, W23.x, tB[2]);  tB[3] = ffma2(bb, W23.y, tB[3]);
            if (nidx < 64) { W01 = nW01; W23 = nW23; }
        }
        ull ai = bcast2(aA[i]);
        cA[0] = ffma2(ai, tA[0], cA[0]);  cA[1] = ffma2(ai, tA[1], cA[1]);
        cA[2] = ffma2(ai, tA[2], cA[2]);  cA[3] = ffma2(ai, tA[3], cA[3]);
        ai = bcast2(aB[i]);
        cB[0] = ffma2(ai, tB[0], cB[0]);  cB[1] = ffma2(ai, tB[1], cB[1]);
        cB[2] = ffma2(ai, tB[2], cB[2]);  cB[3] = ffma2(ai, tB[3], cB[3]);
    }
    unpack2(cA[0], outA[0], outA[1]);  unpack2(cA[1], outA[2], outA[3]);
    unpack2(cA[2], outA[4], outA[5]);  unpack2(cA[3], outA[6], outA[7]);
    unpack2(cB[0], outB[0], outB[1]);  unpack2(cB[1], outB[2], outB[3]);
    unpack2(cB[2], outB[4], outB[5]);  unpack2(cB[3], outB[6], outB[7]);
}

__device__ __forceinline__ void scopy4(float* dst, const float* __restrict__ src, int n4) {
    const float4* s = reinterpret_cast<const float4*>(src);
    float4* d = reinterpret_cast<float4*>(dst);
    for (int i = threadIdx.x; i < n4; i += blockDim.x) d[i] = s[i];
}

__device__ __forceinline__ void store_pair(float4* buf, int b, const float* v) {
    buf[(size_t)b * 2 + 0] = make_float4(v[0], v[1], v[2], v[3]);
    buf[(size_t)b * 2 + 1] = make_float4(v[4], v[5], v[6], v[7]);
}
__device__ __forceinline__ void load_pair(int e, int b, float* v) {
    float4 p0 = __ldg(g_ebuf + ((size_t)e * NB + b) * 2 + 0);
    float4 p1 = __ldg(g_ebuf + ((size_t)e * NB + b) * 2 + 1);
    v[0] = p0.x; v[1] = p0.y; v[2] = p0.z; v[3] = p0.w;
    v[4] = p1.x; v[5] = p1.y; v[6] = p1.z; v[7] = p1.w;
}

// ------------------------------- kernel 1 ----------------------------------
__global__ void __launch_bounds__(T1, 8)
tn_eighth_kernel(const float* __restrict__ x,
                 const float* __restrict__ w7, const float* __restrict__ w6,
                 const float* __restrict__ w5, const float* __restrict__ w4,
                 const float* __restrict__ w3) {
    extern __shared__ float sw[];

    const int e   = blockIdx.x >> 9;      // eighth 0..7
    const int blk = blockIdx.x & 511;

    scopy4(sw + E7, w7 + e * 256,   256 / 4);
    scopy4(sw + E6, w6 + e * 1024, 1024 / 4);
    scopy4(sw + E5, w5 + e * 2048, 2048 / 4);
    scopy4(sw + E4, w4 + e * 1024, 1024 / 4);
    scopy4(sw + E3, w3 + e * 512,   512 / 4);
    __syncthreads();

    const int bA = blk * T1 + threadIdx.x;
    const int bB = bA + HALF;
    const float4* xA = reinterpret_cast<const float4*>(x) + (size_t)bA * 128 + e * 16;
    const float4* xB = reinterpret_cast<const float4*>(x) + (size_t)bB * 128 + e * 16;

    float stkA0[8], stkA1[8], stkA2[8];
    float stkB0[8], stkB1[8], stkB2[8];

#pragma unroll 1
    for (int m = 0; m < 8; ++m) {
        float4 qA0 = __ldg(xA + 2 * m);
        float4 qA1 = __ldg(xA + 2 * m + 1);
        float4 qB0 = __ldg(xB + 2 * m);
        float4 qB1 = __ldg(xB + 2 * m + 1);

        float laA[4], lbA[4], laB[4], lbB[4];
        leaf2(qA0, qB0, sw + E7 + (2 * m) * 16, laA, laB);
        leaf2(qA1, qB1, sw + E7 + (2 * m + 1) * 16, lbA, lbB);

        float curA[8], curB[8];
        contract448_2(laA, lbA, laB, lbB, sw + E6 + m * 128, curA, curB);

        if (!(m & 1)) {
            cp8(stkA0, curA);  cp8(stkB0, curB);
        } else {
            contract888_2(stkA0, curA, stkB0, curB, sw + E5 + (m >> 1) * 512, curA, curB);
            if (!((m >> 1) & 1)) {
                cp8(stkA1, curA);  cp8(stkB1, curB);
            } else {
                contract888_2(stkA1, curA, stkB1, curB, sw + E4 + (m >> 2) * 512, curA, curB);
                if (!((m >> 2) & 1)) {
                    cp8(stkA2, curA);  cp8(stkB2, curB);
                } else {
                    // m == 7: top of this eighth (w3 node)
                    contract888_2(stkA2, curA, stkB2, curB, sw + E3, curA, curB);
                    float4* eb = g_ebuf + ((size_t)e * NB) * 2;
                    store_pair(eb, bA, curA);
                    store_pair(eb, bB, curB);
                }
            }
        }
    }
}

// ------------------------------- kernel 2 ----------------------------------
// 2 warps per CTA (side 0 / side 1), 32 sample-pairs per CTA, grid 1024
// -> ~7 CTAs/SM in a single wave. Each thread: 2 samples x one side
// (chain depth 3: w2, w2, w1), then root after a padded-smem exchange.
__global__ void __launch_bounds__(T2)
tn_merge_kernel(const float* __restrict__ w2, const float* __restrict__ w1,
                const float* __restrict__ w0, float* __restrict__ out) {
    __shared__ float w2s[2048];
    __shared__ float w1s[1024];
    __shared__ float w0s[128];
    __shared__ float xchA[32 * 9];   // hR of sample A (written by side-1 warp)
    __shared__ float xchB[32 * 9];   // hL of sample B (written by side-0 warp)

    scopy4(w2s, w2, 2048 / 4);
    scopy4(w1s, w1, 1024 / 4);
    scopy4(w0s, w0, 128 / 4);
    __syncthreads();

    const int side = threadIdx.x >> 5;  // warp 0: left (eighths 0..3), warp 1: right
    const int lane = threadIdx.x & 31;
    const int bA = blockIdx.x * 32 + lane;
    const int bB = bA + HALF;
    const int eb = side * 4;

    float vA0[8], vA1[8], vB0[8], vB1[8];
    float qA0[8], qB0[8], hA[8], hB[8];

    // first w2 node of this side
    load_pair(eb + 0, bA, vA0);
    load_pair(eb + 1, bA, vA1);
    load_pair(eb + 0, bB, vB0);
    load_pair(eb + 1, bB, vB1);
    contract888_2(vA0, vA1, vB0, vB1, w2s + (2 * side) * 512, qA0, qB0);

    // second w2 node of this side
    load_pair(eb + 2, bA, vA0);
    load_pair(eb + 3, bA, vA1);
    load_pair(eb + 2, bB, vB0);
    load_pair(eb + 3, bB, vB1);
    contract888_2(vA0, vA1, vB0, vB1, w2s + (2 * side + 1) * 512, vA0, vB0);

    // w1 node of this side -> h (this side's half-tree vector)
    contract888_2(qA0, vA0, qB0, vB0, w1s + side * 512, hA, hB);

    // exchange halves
    if (side) {
#pragma unroll
        for (int k = 0; k < 8; ++k) xchA[lane * 9 + k] = hA[k];
    } else {
#pragma unroll
        for (int k = 0; k < 8; ++k) xchB[lane * 9 + k] = hB[k];
    }
    __syncthreads();

    // roots: side-0 warp -> sample A, side-1 warp -> sample B
    float hL[8], hR[8];
    int bo;
    if (side == 0) {
#pragma unroll
        for (int k = 0; k < 8; ++k) { hL[k] = hA[k]; hR[k] = xchA[lane * 9 + k]; }
        bo = bA;
    } else {
#pragma unroll
        for (int k = 0; k < 8; ++k) { hL[k] = xchB[lane * 9 + k]; hR[k] = hB[k]; }
        bo = bB;
    }

    ull acc = 0ull;
#pragma unroll
    for (int i = 0; i < 8; ++i) {
        ull ai = bcast2(hL[i]);
#pragma unroll
        for (int j = 0; j < 8; ++j) {
            ull W = *reinterpret_cast<const ull*>(w0s + (i * 8 + j) * 2);
            acc = ffma2(ffma2(ai, bcast2(hR[j]), 0ull), W, acc);
        }
    }
    float r0, r1;
    unpack2(acc, r0, r1);
    reinterpret_cast<float2*>(out)[bo] = make_float2(r0, r1);
}

extern "C" void kernel_launch(void* const* d_in, const int* in_sizes, int n_in,
                              void* d_out, int out_size) {
    const float* x  = (const float*)d_in[0];
    const float* w7 = (const float*)d_in[1];
    const float* w6 = (const float*)d_in[2];
    const float* w5 = (const float*)d_in[3];
    const float* w4 = (const float*)d_in[4];
    const float* w3 = (const float*)d_in[5];
    const float* w2 = (const float*)d_in[6];
    const float* w1 = (const float*)d_in[7];
    const float* w0 = (const float*)d_in[8];
    float* out = (float*)d_out;

    const size_t smem = SMEM1_FLOATS * sizeof(float);
    cudaFuncSetAttribute(tn_eighth_kernel, cudaFuncAttributeMaxDynamicSharedMemorySize, (int)smem);
    tn_eighth_kernel<<<NBLOCKS1, T1, smem>>>(x, w7, w6, w5, w4, w3);
    tn_merge_kernel<<<NBLOCKS2, T2>>>(w2, w1, w0, out);
}

// round 12
// speedup vs baseline: 1.0399x; 1.0143x over previous
#include <cuda_runtime.h>

// ---------------------------------------------------------------------------
// TNModel binary-tree TN, B=65536. Round 12: SPT=3 in kernel 1.
// Kernel 1: eighth subtree per CTA (w7..w3, 19 KB smem), 64 threads,
//   3 samples/thread (weight LDS amortized over 3), 5 CTAs/SM via
//   __launch_bounds__(64,5) -> 204-reg cap, no spill. Tail block per eighth
//   clamps samples (redundant identical writes, deterministic).
// Kernel 2: side-split merge (R11): 2 samples x one side per thread,
//   chain depth 3, padded-smem exchange, T2=64 grid 1024.
// ---------------------------------------------------------------------------

#define NB       65536
#define T1       64                  // threads, kernel 1
#define SPT      3
#define SPB      (T1 * SPT)          // 192 samples per block
#define BLK_E    342                 // ceil(65536 / 192)
#define NBLOCKS1 (8 * BLK_E)         // 2736
#define HALF     (NB / 2)            // 32768 (merge kernel pairing)
#define T2       64                  // threads, kernel 2
#define NBLOCKS2 (HALF / 32)         // 1024

// eighth-tree shared-memory float offsets
#define E7 0                      // 16 x 16   =  256
#define E6 (E7 + 256)             //  8 x 128  = 1024
#define E5 (E6 + 1024)            //  4 x 512  = 2048
#define E4 (E5 + 2048)            //  2 x 512  = 1024
#define E3 (E4 + 1024)            //  1 x 512  =  512
#define SMEM1_FLOATS (E3 + 512)   // 4864 floats = 19456 bytes

typedef unsigned long long ull;

__device__ float4 g_ebuf[8 * NB * 2];   // [eighth][sample][2 x float4]

__device__ __forceinline__ ull ffma2(ull a, ull b, ull c) {
    ull d;
    asm("fma.rn.f32x2 %0, %1, %2, %3;" : "=l"(d) : "l"(a), "l"(b), "l"(c));
    return d;
}
__device__ __forceinline__ ull bcast2(float x) {
    ull r;
    asm("mov.b64 %0, {%1, %1};" : "=l"(r) : "f"(x));
    return r;
}
__device__ __forceinline__ void unpack2(ull v, float& lo, float& hi) {
    asm("mov.b64 {%0, %1}, %2;" : "=f"(lo), "=f"(hi) : "l"(v));
}
__device__ __forceinline__ void cp8(float* d, const float* s) {
#pragma unroll
    for (int k = 0; k < 8; ++k) d[k] = s[k];
}

// ---- 3-sample primitives (kernel 1) ----------------------------------------

__device__ __forceinline__ void leaf3(float4 qa, float4 qb, float4 qc,
                                      const float* __restrict__ w,
                                      float* hA, float* hB, float* hC) {
    ull cA0 = 0, cA1 = 0, cB0 = 0, cB1 = 0, cC0 = 0, cC1 = 0;
    float eA[2] = {qa.x, qa.y}, oA[2] = {qa.z, qa.w};
    float eB[2] = {qb.x, qb.y}, oB[2] = {qb.z, qb.w};
    float eC[2] = {qc.x, qc.y}, oC[2] = {qc.z, qc.w};
#pragma unroll
    for (int i = 0; i < 2; ++i) {
#pragma unroll
        for (int j = 0; j < 2; ++j) {
            const ulonglong2 W = *reinterpret_cast<const ulonglong2*>(w + (i * 2 + j) * 4);
            ull p = bcast2(eA[i] * oA[j]);
            cA0 = ffma2(p, W.x, cA0);  cA1 = ffma2(p, W.y, cA1);
            p = bcast2(eB[i] * oB[j]);
            cB0 = ffma2(p, W.x, cB0);  cB1 = ffma2(p, W.y, cB1);
            p = bcast2(eC[i] * oC[j]);
            cC0 = ffma2(p, W.x, cC0);  cC1 = ffma2(p, W.y, cC1);
        }
    }
    unpack2(cA0, hA[0], hA[1]);  unpack2(cA1, hA[2], hA[3]);
    unpack2(cB0, hB[0], hB[1]);  unpack2(cB1, hB[2], hB[3]);
    unpack2(cC0, hC[0], hC[1]);  unpack2(cC1, hC[2], hC[3]);
}

__device__ __forceinline__ void contract448_3(const float* aA, const float* bA,
                                              const float* aB, const float* bB,
                                              const float* aC, const float* bC,
                                              const float* __restrict__ w,
                                              float* outA, float* outB, float* outC) {
    ull cA[4] = {0,0,0,0}, cB[4] = {0,0,0,0}, cC[4] = {0,0,0,0};
#pragma unroll
    for (int i = 0; i < 4; ++i) {
        ull tA[4] = {0,0,0,0}, tB[4] = {0,0,0,0}, tC[4] = {0,0,0,0};
#pragma unroll
        for (int j = 0; j < 4; ++j) {
            const ulonglong2* wp = reinterpret_cast<const ulonglong2*>(w + (i * 4 + j) * 8);
            ulonglong2 W01 = wp[0];
            ulonglong2 W23 = wp[1];
            ull bb = bcast2(bA[j]);
            tA[0] = ffma2(bb, W01.x, tA[0]);  tA[1] = ffma2(bb, W01.y, tA[1]);
            tA[2] = ffma2(bb, W23.x, tA[2]);  tA[3] = ffma2(bb, W23.y, tA[3]);
            bb = bcast2(bB[j]);
            tB[0] = ffma2(bb, W01.x, tB[0]);  tB[1] = ffma2(bb, W01.y, tB[1]);
            tB[2] = ffma2(bb, W23.x, tB[2]);  tB[3] = ffma2(bb, W23.y, tB[3]);
            bb = bcast2(bC[j]);
            tC[0] = ffma2(bb, W01.x, tC[0]);  tC[1] = ffma2(bb, W01.y, tC[1]);
            tC[2] = ffma2(bb, W23.x, tC[2]);  tC[3] = ffma2(bb, W23.y, tC[3]);
        }
        ull ai = bcast2(aA[i]);
        cA[0] = ffma2(ai, tA[0], cA[0]);  cA[1] = ffma2(ai, tA[1], cA[1]);
        cA[2] = ffma2(ai, tA[2], cA[2]);  cA[3] = ffma2(ai, tA[3], cA[3]);
        ai = bcast2(aB[i]);
        cB[0] = ffma2(ai, tB[0], cB[0]);  cB[1] = ffma2(ai, tB[1], cB[1]);
        cB[2] = ffma2(ai, tB[2], cB[2]);  cB[3] = ffma2(ai, tB[3], cB[3]);
        ai = bcast2(aC[i]);
        cC[0] = ffma2(ai, tC[0], cC[0]);  cC[1] = ffma2(ai, tC[1], cC[1]);
        cC[2] = ffma2(ai, tC[2], cC[2]);  cC[3] = ffma2(ai, tC[3], cC[3]);
    }
    unpack2(cA[0], outA[0], outA[1]);  unpack2(cA[1], outA[2], outA[3]);
    unpack2(cA[2], outA[4], outA[5]);  unpack2(cA[3], outA[6], outA[7]);
    unpack2(cB[0], outB[0], outB[1]);  unpack2(cB[1], outB[2], outB[3]);
    unpack2(cB[2], outB[4], outB[5]);  unpack2(cB[3], outB[6], outB[7]);
    unpack2(cC[0], outC[0], outC[1]);  unpack2(cC[1], outC[2], outC[3]);
    unpack2(cC[2], outC[4], outC[5]);  unpack2(cC[3], outC[6], outC[7]);
}

// 8x8->8, three samples sharing W (512 floats, smem), prefetch pipeline.
// out may alias b.
__device__ __forceinline__ void contract888_3(const float* aA, const float* bA,
                                              const float* aB, const float* bB,
                                              const float* aC, const float* bC,
                                              const float* __restrict__ w,
                                              float* outA, float* outB, float* outC) {
    const ulonglong2* wp = reinterpret_cast<const ulonglong2*>(w);
    ull cA[4] = {0,0,0,0}, cB[4] = {0,0,0,0}, cC[4] = {0,0,0,0};
    ulonglong2 W01 = wp[0];
    ulonglong2 W23 = wp[1];
#pragma unroll
    for (int i = 0; i < 8; ++i) {
        ull tA[4] = {0,0,0,0}, tB[4] = {0,0,0,0}, tC[4] = {0,0,0,0};
#pragma unroll
        for (int j = 0; j < 8; ++j) {
            const int nidx = i * 8 + j + 1;
            ulonglong2 nW01, nW23;
            if (nidx < 64) {
                nW01 = wp[2 * nidx];
                nW23 = wp[2 * nidx + 1];
            }
            ull bb = bcast2(bA[j]);
            tA[0] = ffma2(bb, W01.x, tA[0]);  tA[1] = ffma2(bb, W01.y, tA[1]);
            tA[2] = ffma2(bb, W23.x, tA[2]);  tA[3] = ffma2(bb, W23.y, tA[3]);
            bb = bcast2(bB[j]);
            tB[0] = ffma2(bb, W01.x, tB[0]);  tB[1] = ffma2(bb, W01.y, tB[1]);
            tB[2] = ffma2(bb, W23.x, tB[2]);  tB[3] = ffma2(bb, W23.y, tB[3]);
            bb = bcast2(bC[j]);
            tC[0] = ffma2(bb, W01.x, tC[0]);  tC[1] = ffma2(bb, W01.y, tC[1]);
            tC[2] = ffma2(bb, W23.x, tC[2]);  tC[3] = ffma2(bb, W23.y, tC[3]);
            if (nidx < 64) { W01 = nW01; W23 = nW23; }
        }
        ull ai = bcast2(aA[i]);
        cA[0] = ffma2(ai, tA[0], cA[0]);  cA[1] = ffma2(ai, tA[1], cA[1]);
        cA[2] = ffma2(ai, tA[2], cA[2]);  cA[3] = ffma2(ai, tA[3], cA[3]);
        ai = bcast2(aB[i]);
        cB[0] = ffma2(ai, tB[0], cB[0]);  cB[1] = ffma2(ai, tB[1], cB[1]);
        cB[2] = ffma2(ai, tB[2], cB[2]);  cB[3] = ffma2(ai, tB[3], cB[3]);
        ai = bcast2(aC[i]);
        cC[0] = ffma2(ai, tC[0], cC[0]);  cC[1] = ffma2(ai, tC[1], cC[1]);
        cC[2] = ffma2(ai, tC[2], cC[2]);  cC[3] = ffma2(ai, tC[3], cC[3]);
    }
    unpack2(cA[0], outA[0], outA[1]);  unpack2(cA[1], outA[2], outA[3]);
    unpack2(cA[2], outA[4], outA[5]);  unpack2(cA[3], outA[6], outA[7]);
    unpack2(cB[0], outB[0], outB[1]);  unpack2(cB[1], outB[2], outB[3]);
    unpack2(cB[2], outB[4], outB[5]);  unpack2(cB[3], outB[6], outB[7]);
    unpack2(cC[0], outC[0], outC[1]);  unpack2(cC[1], outC[2], outC[3]);
    unpack2(cC[2], outC[4], outC[5]);  unpack2(cC[3], outC[6], outC[7]);
}

// ---- 2-sample 8x8x8 (merge kernel, from R11) --------------------------------
__device__ __forceinline__ void contract888_2(const float* aA, const float* bA,
                                              const float* aB, const float* bB,
                                              const float* __restrict__ w,
                                              float* outA, float* outB) {
    const ulonglong2* wp = reinterpret_cast<const ulonglong2*>(w);
    ull cA[4] = {0,0,0,0}, cB[4] = {0,0,0,0};
    ulonglong2 W01 = wp[0];
    ulonglong2 W23 = wp[1];
#pragma unroll
    for (int i = 0; i < 8; ++i) {
        ull tA[4] = {0,0,0,0}, tB[4] = {0,0,0,0};
#pragma unroll
        for (int j = 0; j < 8; ++j) {
            const int nidx = i * 8 + j + 1;
            ulonglong2 nW01, nW23;
            if (nidx < 64) {
                nW01 = wp[2 * nidx];
                nW23 = wp[2 * nidx + 1];
            }
            ull bb = bcast2(bA[j]);
            tA[0] = ffma2(bb, W01.x, tA[0]);  tA[1] = ffma2(bb, W01.y, tA[1]);
            tA[2] = ffma2(bb, W23.x, tA[2]);  tA[3] = ffma2(bb, W23.y, tA[3]);
            bb = bcast2(bB[j]);
            tB[0] = ffma2(bb, W01.x, tB[0]);  tB[1] = ffma2(bb, W01.y, tB[1]);
            tB[2] = ffma2(bb, W23.x, tB[2]);  tB[3] = ffma2(bb, W23.y, tB[3]);
            if (nidx < 64) { W01 = nW01; W23 = nW23; }
        }
        ull ai = bcast2(aA[i]);
        cA[0] = ffma2(ai, tA[0], cA[0]);  cA[1] = ffma2(ai, tA[1], cA[1]);
        cA[2] = ffma2(ai, tA[2], cA[2]);  cA[3] = ffma2(ai, tA[3], cA[3]);
        ai = bcast2(aB[i]);
        cB[0] = ffma2(ai, tB[0], cB[0]);  cB[1] = ffma2(ai, tB[1], cB[1]);
        cB[2] = ffma2(ai, tB[2], cB[2]);  cB[3] = ffma2(ai, tB[3], cB[3]);
    }
    unpack2(cA[0], outA[0], outA[1]);  unpack2(cA[1], outA[2], outA[3]);
    unpack2(cA[2], outA[4], outA[5]);  unpack2(cA[3], outA[6], outA[7]);
    unpack2(cB[0], outB[0], outB[1]);  unpack2(cB[1], outB[2], outB[3]);
    unpack2(cB[2], outB[4], outB[5]);  unpack2(cB[3], outB[6], outB[7]);
}

__device__ __forceinline__ void scopy4(float* dst, const float* __restrict__ src, int n4) {
    const float4* s = reinterpret_cast<const float4*>(src);
    float4* d = reinterpret_cast<float4*>(dst);
    for (int i = threadIdx.x; i < n4; i += blockDim.x) d[i] = s[i];
}

__device__ __forceinline__ void store_pair(float4* buf, int b, const float* v) {
    buf[(size_t)b * 2 + 0] = make_float4(v[0], v[1], v[2], v[3]);
    buf[(size_t)b * 2 + 1] = make_float4(v[4], v[5], v[6], v[7]);
}
__device__ __forceinline__ void load_pair(int e, int b, float* v) {
    float4 p0 = __ldg(g_ebuf + ((size_t)e * NB + b) * 2 + 0);
    float4 p1 = __ldg(g_ebuf + ((size_t)e * NB + b) * 2 + 1);
    v[0] = p0.x; v[1] = p0.y; v[2] = p0.z; v[3] = p0.w;
    v[4] = p1.x; v[5] = p1.y; v[6] = p1.z; v[7] = p1.w;
}

// ------------------------------- kernel 1 ----------------------------------
__global__ void __launch_bounds__(T1, 5)
tn_eighth_kernel(const float* __restrict__ x,
                 const float* __restrict__ w7, const float* __restrict__ w6,
                 const float* __restrict__ w5, const float* __restrict__ w4,
                 const float* __restrict__ w3) {
    extern __shared__ float sw[];

    const int e   = blockIdx.x / BLK_E;      // eighth 0..7
    const int blk = blockIdx.x - e * BLK_E;  // 0..341

    scopy4(sw + E7, w7 + e * 256,   256 / 4);
    scopy4(sw + E6, w6 + e * 1024, 1024 / 4);
    scopy4(sw + E5, w5 + e * 2048, 2048 / 4);
    scopy4(sw + E4, w4 + e * 1024, 1024 / 4);
    scopy4(sw + E3, w3 + e * 512,   512 / 4);
    __syncthreads();

    // three samples per thread; tail block clamps duplicates (identical writes)
    const int b0 = blk * SPB + threadIdx.x;
    int b1 = b0 + T1;
    int b2 = b0 + 2 * T1;
    if (b1 >= NB) b1 = b0;
    if (b2 >= NB) b2 = b0;

    const float4* xA = reinterpret_cast<const float4*>(x) + (size_t)b0 * 128 + e * 16;
    const float4* xB = reinterpret_cast<const float4*>(x) + (size_t)b1 * 128 + e * 16;
    const float4* xC = reinterpret_cast<const float4*>(x) + (size_t)b2 * 128 + e * 16;

    float stkA0[8], stkA1[8], stkA2[8];
    float stkB0[8], stkB1[8], stkB2[8];
    float stkC0[8], stkC1[8], stkC2[8];

#pragma unroll 1
    for (int m = 0; m < 8; ++m) {
        float4 qA0 = __ldg(xA + 2 * m);
        float4 qA1 = __ldg(xA + 2 * m + 1);
        float4 qB0 = __ldg(xB + 2 * m);
        float4 qB1 = __ldg(xB + 2 * m + 1);
        float4 qC0 = __ldg(xC + 2 * m);
        float4 qC1 = __ldg(xC + 2 * m + 1);

        float laA[4], lbA[4], laB[4], lbB[4], laC[4], lbC[4];
        leaf3(qA0, qB0, qC0, sw + E7 + (2 * m) * 16, laA, laB, laC);
        leaf3(qA1, qB1, qC1, sw + E7 + (2 * m + 1) * 16, lbA, lbB, lbC);

        float curA[8], curB[8], curC[8];
        contract448_3(laA, lbA, laB, lbB, laC, lbC, sw + E6 + m * 128,
                      curA, curB, curC);

        if (!(m & 1)) {
            cp8(stkA0, curA);  cp8(stkB0, curB);  cp8(stkC0, curC);
        } else {
            contract888_3(stkA0, curA, stkB0, curB, stkC0, curC,
                          sw + E5 + (m >> 1) * 512, curA, curB, curC);
            if (!((m >> 1) & 1)) {
                cp8(stkA1, curA);  cp8(stkB1, curB);  cp8(stkC1, curC);
            } else {
                contract888_3(stkA1, curA, stkB1, curB, stkC1, curC,
                              sw + E4 + (m >> 2) * 512, curA, curB, curC);
                if (!((m >> 2) & 1)) {
                    cp8(stkA2, curA);  cp8(stkB2, curB);  cp8(stkC2, curC);
                } else {
                    // m == 7: top of this eighth (w3 node)
                    contract888_3(stkA2, curA, stkB2, curB, stkC2, curC,
                                  sw + E3, curA, curB, curC);
                    float4* eb = g_ebuf + ((size_t)e * NB) * 2;
                    store_pair(eb, b0, curA);
                    store_pair(eb, b1, curB);
                    store_pair(eb, b2, curC);
                }
            }
        }
    }
}

// ------------------------------- kernel 2 ----------------------------------
// 2 warps per CTA (side 0 / side 1), 32 sample-pairs per CTA, grid 1024.
__global__ void __launch_bounds__(T2)
tn_merge_kernel(const float* __restrict__ w2, const float* __restrict__ w1,
                const float* __restrict__ w0, float* __restrict__ out) {
    __shared__ float w2s[2048];
    __shared__ float w1s[1024];
    __shared__ float w0s[128];
    __shared__ float xchA[32 * 9];
    __shared__ float xchB[32 * 9];

    scopy4(w2s, w2, 2048 / 4);
    scopy4(w1s, w1, 1024 / 4);
    scopy4(w0s, w0, 128 / 4);
    __syncthreads();

    const int side = threadIdx.x >> 5;
    const int lane = threadIdx.x & 31;
    const int bA = blockIdx.x * 32 + lane;
    const int bB = bA + HALF;
    const int eb = side * 4;

    float vA0[8], vA1[8], vB0[8], vB1[8];
    float qA0[8], qB0[8], hA[8], hB[8];

    load_pair(eb + 0, bA, vA0);
    load_pair(eb + 1, bA, vA1);
    load_pair(eb + 0, bB, vB0);
    load_pair(eb + 1, bB, vB1);
    contract888_2(vA0, vA1, vB0, vB1, w2s + (2 * side) * 512, qA0, qB0);

    load_pair(eb + 2, bA, vA0);
    load_pair(eb + 3, bA, vA1);
    load_pair(eb + 2, bB, vB0);
    load_pair(eb + 3, bB, vB1);
    contract888_2(vA0, vA1, vB0, vB1, w2s + (2 * side + 1) * 512, vA0, vB0);

    contract888_2(qA0, vA0, qB0, vB0, w1s + side * 512, hA, hB);

    if (side) {
#pragma unroll
        for (int k = 0; k < 8; ++k) xchA[lane * 9 + k] = hA[k];
    } else {
#pragma unroll
        for (int k = 0; k < 8; ++k) xchB[lane * 9 + k] = hB[k];
    }
    __syncthreads();

    float hL[8], hR[8];
    int bo;
    if (side == 0) {
#pragma unroll
        for (int k = 0; k < 8; ++k) { hL[k] = hA[k]; hR[k] = xchA[lane * 9 + k]; }
        bo = bA;
    } else {
#pragma unroll
        for (int k = 0; k < 8; ++k) { hL[k] = xchB[lane * 9 + k]; hR[k] = hB[k]; }
        bo = bB;
    }

    ull acc = 0ull;
#pragma unroll
    for (int i = 0; i < 8; ++i) {
        ull ai = bcast2(hL[i]);
#pragma unroll
        for (int j = 0; j < 8; ++j) {
            ull W = *reinterpret_cast<const ull*>(w0s + (i * 8 + j) * 2);
            acc = ffma2(ffma2(ai, bcast2(hR[j]), 0ull), W, acc);
        }
    }
    float r0, r1;
    unpack2(acc, r0, r1);
    reinterpret_cast<float2*>(out)[bo] = make_float2(r0, r1);
}

extern "C" void kernel_launch(void* const* d_in, const int* in_sizes, int n_in,
                              void* d_out, int out_size) {
    const float* x  = (const float*)d_in[0];
    const float* w7 = (const float*)d_in[1];
    const float* w6 = (const float*)d_in[2];
    const float* w5 = (const float*)d_in[3];
    const float* w4 = (const float*)d_in[4];
    const float* w3 = (const float*)d_in[5];
    const float* w2 = (const float*)d_in[6];
    const float* w1 = (const float*)d_in[7];
    const float* w0 = (const float*)d_in[8];
    float* out = (float*)d_out;

    const size_t smem = SMEM1_FLOATS * sizeof(float);
    cudaFuncSetAttribute(tn_eighth_kernel, cudaFuncAttributeMaxDynamicSharedMemorySize, (int)smem);
    tn_eighth_kernel<<<NBLOCKS1, T1, smem>>>(x, w7, w6, w5, w4, w3);
    tn_merge_kernel<<<NBLOCKS2, T2>>>(w2, w1, w0, out);
}

// round 13
// speedup vs baseline: 1.0498x; 1.0095x over previous
#include <cuda_runtime.h>

// ---------------------------------------------------------------------------
// TNModel binary-tree TN, B=65536. Round 13:
// Kernel 1: eighth subtree per CTA (w7..w3, 19 KB smem), 64 threads,
//   3 samples/thread, 5 CTAs/SM; weight-prefetch distance 2 (>= LDS latency).
// Kernel 2: stage-split merge: T2=128 (4 warps), 32 sample-pairs per CTA.
//   Stage1: warp w -> w2 node w (2-sample ILP). Stage2: warp -> one w1 eval.
//   Stage3: roots on warps 0-1. Chains 3x shorter, 2x warps/SM.
// ---------------------------------------------------------------------------

#define NB       65536
#define T1       64                  // threads, kernel 1
#define SPT      3
#define SPB      (T1 * SPT)          // 192 samples per block
#define BLK_E    342                 // ceil(65536 / 192)
#define NBLOCKS1 (8 * BLK_E)         // 2736
#define HALF     (NB / 2)            // 32768
#define T2       128                 // threads, kernel 2
#define NBLOCKS2 (HALF / 32)         // 1024 (32 sample-pairs per CTA)

// eighth-tree shared-memory float offsets
#define E7 0                      // 16 x 16   =  256
#define E6 (E7 + 256)             //  8 x 128  = 1024
#define E5 (E6 + 1024)            //  4 x 512  = 2048
#define E4 (E5 + 2048)            //  2 x 512  = 1024
#define E3 (E4 + 1024)            //  1 x 512  =  512
#define SMEM1_FLOATS (E3 + 512)   // 4864 floats = 19456 bytes

typedef unsigned long long ull;

__device__ float4 g_ebuf[8 * NB * 2];   // [eighth][sample][2 x float4]

__device__ __forceinline__ ull ffma2(ull a, ull b, ull c) {
    ull d;
    asm("fma.rn.f32x2 %0, %1, %2, %3;" : "=l"(d) : "l"(a), "l"(b), "l"(c));
    return d;
}
__device__ __forceinline__ ull bcast2(float x) {
    ull r;
    asm("mov.b64 %0, {%1, %1};" : "=l"(r) : "f"(x));
    return r;
}
__device__ __forceinline__ void unpack2(ull v, float& lo, float& hi) {
    asm("mov.b64 {%0, %1}, %2;" : "=f"(lo), "=f"(hi) : "l"(v));
}
__device__ __forceinline__ void cp8(float* d, const float* s) {
#pragma unroll
    for (int k = 0; k < 8; ++k) d[k] = s[k];
}

// ---- 3-sample primitives (kernel 1) ----------------------------------------

__device__ __forceinline__ void leaf3(float4 qa, float4 qb, float4 qc,
                                      const float* __restrict__ w,
                                      float* hA, float* hB, float* hC) {
    ull cA0 = 0, cA1 = 0, cB0 = 0, cB1 = 0, cC0 = 0, cC1 = 0;
    float eA[2] = {qa.x, qa.y}, oA[2] = {qa.z, qa.w};
    float eB[2] = {qb.x, qb.y}, oB[2] = {qb.z, qb.w};
    float eC[2] = {qc.x, qc.y}, oC[2] = {qc.z, qc.w};
#pragma unroll
    for (int i = 0; i < 2; ++i) {
#pragma unroll
        for (int j = 0; j < 2; ++j) {
            const ulonglong2 W = *reinterpret_cast<const ulonglong2*>(w + (i * 2 + j) * 4);
            ull p = bcast2(eA[i] * oA[j]);
            cA0 = ffma2(p, W.x, cA0);  cA1 = ffma2(p, W.y, cA1);
            p = bcast2(eB[i] * oB[j]);
            cB0 = ffma2(p, W.x, cB0);  cB1 = ffma2(p, W.y, cB1);
            p = bcast2(eC[i] * oC[j]);
            cC0 = ffma2(p, W.x, cC0);  cC1 = ffma2(p, W.y, cC1);
        }
    }
    unpack2(cA0, hA[0], hA[1]);  unpack2(cA1, hA[2], hA[3]);
    unpack2(cB0, hB[0], hB[1]);  unpack2(cB1, hB[2], hB[3]);
    unpack2(cC0, hC[0], hC[1]);  unpack2(cC1, hC[2], hC[3]);
}

__device__ __forceinline__ void contract448_3(const float* aA, const float* bA,
                                              const float* aB, const float* bB,
                                              const float* aC, const float* bC,
                                              const float* __restrict__ w,
                                              float* outA, float* outB, float* outC) {
    ull cA[4] = {0,0,0,0}, cB[4] = {0,0,0,0}, cC[4] = {0,0,0,0};
#pragma unroll
    for (int i = 0; i < 4; ++i) {
        ull tA[4] = {0,0,0,0}, tB[4] = {0,0,0,0}, tC[4] = {0,0,0,0};
#pragma unroll
        for (int j = 0; j < 4; ++j) {
            const ulonglong2* wp = reinterpret_cast<const ulonglong2*>(w + (i * 4 + j) * 8);
            ulonglong2 W01 = wp[0];
            ulonglong2 W23 = wp[1];
            ull bb = bcast2(bA[j]);
            tA[0] = ffma2(bb, W01.x, tA[0]);  tA[1] = ffma2(bb, W01.y, tA[1]);
            tA[2] = ffma2(bb, W23.x, tA[2]);  tA[3] = ffma2(bb, W23.y, tA[3]);
            bb = bcast2(bB[j]);
            tB[0] = ffma2(bb, W01.x, tB[0]);  tB[1] = ffma2(bb, W01.y, tB[1]);
            tB[2] = ffma2(bb, W23.x, tB[2]);  tB[3] = ffma2(bb, W23.y, tB[3]);
            bb = bcast2(bC[j]);
            tC[0] = ffma2(bb, W01.x, tC[0]);  tC[1] = ffma2(bb, W01.y, tC[1]);
            tC[2] = ffma2(bb, W23.x, tC[2]);  tC[3] = ffma2(bb, W23.y, tC[3]);
        }
        ull ai = bcast2(aA[i]);
        cA[0] = ffma2(ai, tA[0], cA[0]);  cA[1] = ffma2(ai, tA[1], cA[1]);
        cA[2] = ffma2(ai, tA[2], cA[2]);  cA[3] = ffma2(ai, tA[3], cA[3]);
        ai = bcast2(aB[i]);
        cB[0] = ffma2(ai, tB[0], cB[0]);  cB[1] = ffma2(ai, tB[1], cB[1]);
        cB[2] = ffma2(ai, tB[2], cB[2]);  cB[3] = ffma2(ai, tB[3], cB[3]);
        ai = bcast2(aC[i]);
        cC[0] = ffma2(ai, tC[0], cC[0]);  cC[1] = ffma2(ai, tC[1], cC[1]);
        cC[2] = ffma2(ai, tC[2], cC[2]);  cC[3] = ffma2(ai, tC[3], cC[3]);
    }
    unpack2(cA[0], outA[0], outA[1]);  unpack2(cA[1], outA[2], outA[3]);
    unpack2(cA[2], outA[4], outA[5]);  unpack2(cA[3], outA[6], outA[7]);
    unpack2(cB[0], outB[0], outB[1]);  unpack2(cB[1], outB[2], outB[3]);
    unpack2(cB[2], outB[4], outB[5]);  unpack2(cB[3], outB[6], outB[7]);
    unpack2(cC[0], outC[0], outC[1]);  unpack2(cC[1], outC[2], outC[3]);
    unpack2(cC[2], outC[4], outC[5]);  unpack2(cC[3], outC[6], outC[7]);
}

// 8x8->8, three samples sharing W (512 floats, smem), prefetch distance 2.
// out may alias b. (loops fully unrolled: pipeline copies rename away)
__device__ __forceinline__ void contract888_3(const float* aA, const float* bA,
                                              const float* aB, const float* bB,
                                              const float* aC, const float* bC,
                                              const float* __restrict__ w,
                                              float* outA, float* outB, float* outC) {
    const ulonglong2* wp = reinterpret_cast<const ulonglong2*>(w);
    ull cA[4] = {0,0,0,0}, cB[4] = {0,0,0,0}, cC[4] = {0,0,0,0};
    ulonglong2 W0a = wp[0], W0b = wp[1];   // weights for current idx
    ulonglong2 W1a = wp[2], W1b = wp[3];   // weights for idx+1
#pragma unroll
    for (int i = 0; i < 8; ++i) {
        ull tA[4] = {0,0,0,0}, tB[4] = {0,0,0,0}, tC[4] = {0,0,0,0};
#pragma unroll
        for (int j = 0; j < 8; ++j) {
            const int nidx = i * 8 + j + 2;
            ulonglong2 nWa, nWb;
            if (nidx < 64) {
                nWa = wp[2 * nidx];
                nWb = wp[2 * nidx + 1];
            }
            ull bb = bcast2(bA[j]);
            tA[0] = ffma2(bb, W0a.x, tA[0]);  tA[1] = ffma2(bb, W0a.y, tA[1]);
            tA[2] = ffma2(bb, W0b.x, tA[2]);  tA[3] = ffma2(bb, W0b.y, tA[3]);
            bb = bcast2(bB[j]);
            tB[0] = ffma2(bb, W0a.x, tB[0]);  tB[1] = ffma2(bb, W0a.y, tB[1]);
            tB[2] = ffma2(bb, W0b.x, tB[2]);  tB[3] = ffma2(bb, W0b.y, tB[3]);
            bb = bcast2(bC[j]);
            tC[0] = ffma2(bb, W0a.x, tC[0]);  tC[1] = ffma2(bb, W0a.y, tC[1]);
            tC[2] = ffma2(bb, W0b.x, tC[2]);  tC[3] = ffma2(bb, W0b.y, tC[3]);
            // slide the 2-deep pipeline
            W0a = W1a;  W0b = W1b;
            if (nidx < 64) { W1a = nWa; W1b = nWb; }
        }
        ull ai = bcast2(aA[i]);
        cA[0] = ffma2(ai, tA[0], cA[0]);  cA[1] = ffma2(ai, tA[1], cA[1]);
        cA[2] = ffma2(ai, tA[2], cA[2]);  cA[3] = ffma2(ai, tA[3], cA[3]);
        ai = bcast2(aB[i]);
        cB[0] = ffma2(ai, tB[0], cB[0]);  cB[1] = ffma2(ai, tB[1], cB[1]);
        cB[2] = ffma2(ai, tB[2], cB[2]);  cB[3] = ffma2(ai, tB[3], cB[3]);
        ai = bcast2(aC[i]);
        cC[0] = ffma2(ai, tC[0], cC[0]);  cC[1] = ffma2(ai, tC[1], cC[1]);
        cC[2] = ffma2(ai, tC[2], cC[2]);  cC[3] = ffma2(ai, tC[3], cC[3]);
    }
    unpack2(cA[0], outA[0], outA[1]);  unpack2(cA[1], outA[2], outA[3]);
    unpack2(cA[2], outA[4], outA[5]);  unpack2(cA[3], outA[6], outA[7]);
    unpack2(cB[0], outB[0], outB[1]);  unpack2(cB[1], outB[2], outB[3]);
    unpack2(cB[2], outB[4], outB[5]);  unpack2(cB[3], outB[6], outB[7]);
    unpack2(cC[0], outC[0], outC[1]);  unpack2(cC[1], outC[2], outC[3]);
    unpack2(cC[2], outC[4], outC[5]);  unpack2(cC[3], outC[6], outC[7]);
}

// ---- 2-sample and 1-sample 8x8x8 (merge kernel) -----------------------------
__device__ __forceinline__ void contract888_2(const float* aA, const float* bA,
                                              const float* aB, const float* bB,
                                              const float* __restrict__ w,
                                              float* outA, float* outB) {
    const ulonglong2* wp = reinterpret_cast<const ulonglong2*>(w);
    ull cA[4] = {0,0,0,0}, cB[4] = {0,0,0,0};
    ulonglong2 W0a = wp[0], W0b = wp[1];
    ulonglong2 W1a = wp[2], W1b = wp[3];
#pragma unroll
    for (int i = 0; i < 8; ++i) {
        ull tA[4] = {0,0,0,0}, tB[4] = {0,0,0,0};
#pragma unroll
        for (int j = 0; j < 8; ++j) {
            const int nidx = i * 8 + j + 2;
            ulonglong2 nWa, nWb;
            if (nidx < 64) {
                nWa = wp[2 * nidx];
                nWb = wp[2 * nidx + 1];
            }
            ull bb = bcast2(bA[j]);
            tA[0] = ffma2(bb, W0a.x, tA[0]);  tA[1] = ffma2(bb, W0a.y, tA[1]);
            tA[2] = ffma2(bb, W0b.x, tA[2]);  tA[3] = ffma2(bb, W0b.y, tA[3]);
            bb = bcast2(bB[j]);
            tB[0] = ffma2(bb, W0a.x, tB[0]);  tB[1] = ffma2(bb, W0a.y, tB[1]);
            tB[2] = ffma2(bb, W0b.x, tB[2]);  tB[3] = ffma2(bb, W0b.y, tB[3]);
            W0a = W1a;  W0b = W1b;
            if (nidx < 64) { W1a = nWa; W1b = nWb; }
        }
        ull ai = bcast2(aA[i]);
        cA[0] = ffma2(ai, tA[0], cA[0]);  cA[1] = ffma2(ai, tA[1], cA[1]);
        cA[2] = ffma2(ai, tA[2], cA[2]);  cA[3] = ffma2(ai, tA[3], cA[3]);
        ai = bcast2(aB[i]);
        cB[0] = ffma2(ai, tB[0], cB[0]);  cB[1] = ffma2(ai, tB[1], cB[1]);
        cB[2] = ffma2(ai, tB[2], cB[2]);  cB[3] = ffma2(ai, tB[3], cB[3]);
    }
    unpack2(cA[0], outA[0], outA[1]);  unpack2(cA[1], outA[2], outA[3]);
    unpack2(cA[2], outA[4], outA[5]);  unpack2(cA[3], outA[6], outA[7]);
    unpack2(cB[0], outB[0], outB[1]);  unpack2(cB[1], outB[2], outB[3]);
    unpack2(cB[2], outB[4], outB[5]);  unpack2(cB[3], outB[6], outB[7]);
}

__device__ __forceinline__ void contract888_1(const float* a, const float* b,
                                              const float* __restrict__ w, float* out) {
    const ulonglong2* wp = reinterpret_cast<const ulonglong2*>(w);
    ull c[4] = {0,0,0,0};
    ulonglong2 W0a = wp[0], W0b = wp[1];
    ulonglong2 W1a = wp[2], W1b = wp[3];
#pragma unroll
    for (int i = 0; i < 8; ++i) {
        ull t[4] = {0,0,0,0};
#pragma unroll
        for (int j = 0; j < 8; ++j) {
            const int nidx = i * 8 + j + 2;
            ulonglong2 nWa, nWb;
            if (nidx < 64) {
                nWa = wp[2 * nidx];
                nWb = wp[2 * nidx + 1];
            }
            ull bb = bcast2(b[j]);
            t[0] = ffma2(bb, W0a.x, t[0]);  t[1] = ffma2(bb, W0a.y, t[1]);
            t[2] = ffma2(bb, W0b.x, t[2]);  t[3] = ffma2(bb, W0b.y, t[3]);
            W0a = W1a;  W0b = W1b;
            if (nidx < 64) { W1a = nWa; W1b = nWb; }
        }
        ull ai = bcast2(a[i]);
        c[0] = ffma2(ai, t[0], c[0]);  c[1] = ffma2(ai, t[1], c[1]);
        c[2] = ffma2(ai, t[2], c[2]);  c[3] = ffma2(ai, t[3], c[3]);
    }
    unpack2(c[0], out[0], out[1]);  unpack2(c[1], out[2], out[3]);
    unpack2(c[2], out[4], out[5]);  unpack2(c[3], out[6], out[7]);
}

__device__ __forceinline__ void scopy4(float* dst, const float* __restrict__ src, int n4) {
    const float4* s = reinterpret_cast<const float4*>(src);
    float4* d = reinterpret_cast<float4*>(dst);
    for (int i = threadIdx.x; i < n4; i += blockDim.x) d[i] = s[i];
}

__device__ __forceinline__ void store_pair(float4* buf, int b, const float* v) {
    buf[(size_t)b * 2 + 0] = make_float4(v[0], v[1], v[2], v[3]);
    buf[(size_t)b * 2 + 1] = make_float4(v[4], v[5], v[6], v[7]);
}
__device__ __forceinline__ void load_pair(int e, int b, float* v) {
    float4 p0 = __ldg(g_ebuf + ((size_t)e * NB + b) * 2 + 0);
    float4 p1 = __ldg(g_ebuf + ((size_t)e * NB + b) * 2 + 1);
    v[0] = p0.x; v[1] = p0.y; v[2] = p0.z; v[3] = p0.w;
    v[4] = p1.x; v[5] = p1.y; v[6] = p1.z; v[7] = p1.w;
}

// ------------------------------- kernel 1 ----------------------------------
__global__ void __launch_bounds__(T1, 5)
tn_eighth_kernel(const float* __restrict__ x,
                 const float* __restrict__ w7, const float* __restrict__ w6,
                 const float* __restrict__ w5, const float* __restrict__ w4,
                 const float* __restrict__ w3) {
    extern __shared__ float sw[];

    const int e   = blockIdx.x / BLK_E;      // eighth 0..7
    const int blk = blockIdx.x - e * BLK_E;  // 0..341

    scopy4(sw + E7, w7 + e * 256,   256 / 4);
    scopy4(sw + E6, w6 + e * 1024, 1024 / 4);
    scopy4(sw + E5, w5 + e * 2048, 2048 / 4);
    scopy4(sw + E4, w4 + e * 1024, 1024 / 4);
    scopy4(sw + E3, w3 + e * 512,   512 / 4);
    __syncthreads();

    const int b0 = blk * SPB + threadIdx.x;
    int b1 = b0 + T1;
    int b2 = b0 + 2 * T1;
    if (b1 >= NB) b1 = b0;
    if (b2 >= NB) b2 = b0;

    const float4* xA = reinterpret_cast<const float4*>(x) + (size_t)b0 * 128 + e * 16;
    const float4* xB = reinterpret_cast<const float4*>(x) + (size_t)b1 * 128 + e * 16;
    const float4* xC = reinterpret_cast<const float4*>(x) + (size_t)b2 * 128 + e * 16;

    float stkA0[8], stkA1[8], stkA2[8];
    float stkB0[8], stkB1[8], stkB2[8];
    float stkC0[8], stkC1[8], stkC2[8];

#pragma unroll 1
    for (int m = 0; m < 8; ++m) {
        float4 qA0 = __ldg(xA + 2 * m);
        float4 qA1 = __ldg(xA + 2 * m + 1);
        float4 qB0 = __ldg(xB + 2 * m);
        float4 qB1 = __ldg(xB + 2 * m + 1);
        float4 qC0 = __ldg(xC + 2 * m);
        float4 qC1 = __ldg(xC + 2 * m + 1);

        float laA[4], lbA[4], laB[4], lbB[4], laC[4], lbC[4];
        leaf3(qA0, qB0, qC0, sw + E7 + (2 * m) * 16, laA, laB, laC);
        leaf3(qA1, qB1, qC1, sw + E7 + (2 * m + 1) * 16, lbA, lbB, lbC);

        float curA[8], curB[8], curC[8];
        contract448_3(laA, lbA, laB, lbB, laC, lbC, sw + E6 + m * 128,
                      curA, curB, curC);

        if (!(m & 1)) {
            cp8(stkA0, curA);  cp8(stkB0, curB);  cp8(stkC0, curC);
        } else {
            contract888_3(stkA0, curA, stkB0, curB, stkC0, curC,
                          sw + E5 + (m >> 1) * 512, curA, curB, curC);
            if (!((m >> 1) & 1)) {
                cp8(stkA1, curA);  cp8(stkB1, curB);  cp8(stkC1, curC);
            } else {
                contract888_3(stkA1, curA, stkB1, curB, stkC1, curC,
                              sw + E4 + (m >> 2) * 512, curA, curB, curC);
                if (!((m >> 2) & 1)) {
                    cp8(stkA2, curA);  cp8(stkB2, curB);  cp8(stkC2, curC);
                } else {
                    // m == 7: top of this eighth (w3 node)
                    contract888_3(stkA2, curA, stkB2, curB, stkC2, curC,
                                  sw + E3, curA, curB, curC);
                    float4* eb = g_ebuf + ((size_t)e * NB) * 2;
                    store_pair(eb, b0, curA);
                    store_pair(eb, b1, curB);
                    store_pair(eb, b2, curC);
                }
            }
        }
    }
}

// ------------------------------- kernel 2 ----------------------------------
// 4 warps per CTA, 32 sample-pairs per CTA, grid 1024 -> ~28 warps/SM.
// Stage1: warp w computes w2 node w for its 32 pairs (2-sample ILP).
// Stage2: warp (side=w>>1, class=w&1) computes one w1 eval per lane.
// Stage3: warps 0 (class A) and 1 (class B) compute roots.
__global__ void __launch_bounds__(T2)
tn_merge_kernel(const float* __restrict__ w2, const float* __restrict__ w1,
                const float* __restrict__ w0, float* __restrict__ out) {
    __shared__ float w2s[2048];
    __shared__ float w1s[1024];
    __shared__ float w0s[128];
    __shared__ float x1[4][2][32 * 9];   // stage1: [w2 node][class A/B][lane]
    __shared__ float x2[2][2][32 * 9];   // stage2: [side L/R][class A/B][lane]

    scopy4(w2s, w2, 2048 / 4);
    scopy4(w1s, w1, 1024 / 4);
    scopy4(w0s, w0, 128 / 4);
    __syncthreads();

    const int warp = threadIdx.x >> 5;
    const int lane = threadIdx.x & 31;
    const int bA = blockIdx.x * 32 + lane;
    const int bB = bA + HALF;

    // ---- stage 1: w2 node = warp (eighths 2*warp, 2*warp+1) ----
    {
        float vA0[8], vA1[8], vB0[8], vB1[8], qA[8], qB[8];
        load_pair(2 * warp + 0, bA, vA0);
        load_pair(2 * warp + 1, bA, vA1);
        load_pair(2 * warp + 0, bB, vB0);
        load_pair(2 * warp + 1, bB, vB1);
        contract888_2(vA0, vA1, vB0, vB1, w2s + warp * 512, qA, qB);
#pragma unroll
        for (int k = 0; k < 8; ++k) {
            x1[warp][0][lane * 9 + k] = qA[k];
            x1[warp][1][lane * 9 + k] = qB[k];
        }
    }
    __syncthreads();

    // ---- stage 2: one w1 eval per warp ----
    const int side = warp >> 1;   // 0: left (w2 nodes 0,1), 1: right (2,3)
    const int cls  = warp & 1;    // 0: sample A, 1: sample B
    {
        float a[8], b[8], h[8];
#pragma unroll
        for (int k = 0; k < 8; ++k) {
            a[k] = x1[2 * side + 0][cls][lane * 9 + k];
            b[k] = x1[2 * side + 1][cls][lane * 9 + k];
        }
        contract888_1(a, b, w1s + side * 512, h);
#pragma unroll
        for (int k = 0; k < 8; ++k) x2[side][cls][lane * 9 + k] = h[k];
    }
    __syncthreads();

    // ---- stage 3: roots (warp 0 -> sample A, warp 1 -> sample B) ----
    if (warp < 2) {
        const int c  = warp;
        const int bo = c == 0 ? bA : bB;
        float hL[8], hR[8];
#pragma unroll
        for (int k = 0; k < 8; ++k) {
            hL[k] = x2[0][c][lane * 9 + k];
            hR[k] = x2[1][c][lane * 9 + k];
        }
        ull acc = 0ull;
#pragma unroll
        for (int i = 0; i < 8; ++i) {
            ull ai = bcast2(hL[i]);
#pragma unroll
            for (int j = 0; j < 8; ++j) {
                ull W = *reinterpret_cast<const ull*>(w0s + (i * 8 + j) * 2);
                acc = ffma2(ffma2(ai, bcast2(hR[j]), 0ull), W, acc);
            }
        }
        float r0, r1;
        unpack2(acc, r0, r1);
        reinterpret_cast<float2*>(out)[bo] = make_float2(r0, r1);
    }
}

extern "C" void kernel_launch(void* const* d_in, const int* in_sizes, int n_in,
                              void* d_out, int out_size) {
    const float* x  = (const float*)d_in[0];
    const float* w7 = (const float*)d_in[1];
    const float* w6 = (const float*)d_in[2];
    const float* w5 = (const float*)d_in[3];
    const float* w4 = (const float*)d_in[4];
    const float* w3 = (const float*)d_in[5];
    const float* w2 = (const float*)d_in[6];
    const float* w1 = (const float*)d_in[7];
    const float* w0 = (const float*)d_in[8];
    float* out = (float*)d_out;

    const size_t smem = SMEM1_FLOATS * sizeof(float);
    cudaFuncSetAttribute(tn_eighth_kernel, cudaFuncAttributeMaxDynamicSharedMemorySize, (int)smem);
    tn_eighth_kernel<<<NBLOCKS1, T1, smem>>>(x, w7, w6, w5, w4, w3);
    tn_merge_kernel<<<NBLOCKS2, T2>>>(w2, w1, w0, out);
}

// round 14
// speedup vs baseline: 1.0583x; 1.0080x over previous
#include <cuda_runtime.h>

// ---------------------------------------------------------------------------
// TNModel binary-tree TN, B=65536. Round 14:
// Kernel 1: eighth subtree per CTA (w7..w3, 19 KB smem), 64 threads,
//   3 samples/thread, 5 CTAs/SM, prefetch distance 2. x loads use __ldcs
//   (evict-first) so g_ebuf stays L2-resident for the merge kernel.
// Kernel 2: stage-split merge (R13) with g_ebuf loads hoisted above the
//   weight-staging barrier (overlap global latency with smem staging).
// ---------------------------------------------------------------------------

#define NB       65536
#define T1       64                  // threads, kernel 1
#define SPT      3
#define SPB      (T1 * SPT)          // 192 samples per block
#define BLK_E    342                 // ceil(65536 / 192)
#define NBLOCKS1 (8 * BLK_E)         // 2736
#define HALF     (NB / 2)            // 32768
#define T2       128                 // threads, kernel 2
#define NBLOCKS2 (HALF / 32)         // 1024 (32 sample-pairs per CTA)

// eighth-tree shared-memory float offsets
#define E7 0                      // 16 x 16   =  256
#define E6 (E7 + 256)             //  8 x 128  = 1024
#define E5 (E6 + 1024)            //  4 x 512  = 2048
#define E4 (E5 + 2048)            //  2 x 512  = 1024
#define E3 (E4 + 1024)            //  1 x 512  =  512
#define SMEM1_FLOATS (E3 + 512)   // 4864 floats = 19456 bytes

typedef unsigned long long ull;

__device__ float4 g_ebuf[8 * NB * 2];   // [eighth][sample][2 x float4]

__device__ __forceinline__ ull ffma2(ull a, ull b, ull c) {
    ull d;
    asm("fma.rn.f32x2 %0, %1, %2, %3;" : "=l"(d) : "l"(a), "l"(b), "l"(c));
    return d;
}
__device__ __forceinline__ ull bcast2(float x) {
    ull r;
    asm("mov.b64 %0, {%1, %1};" : "=l"(r) : "f"(x));
    return r;
}
__device__ __forceinline__ void unpack2(ull v, float& lo, float& hi) {
    asm("mov.b64 {%0, %1}, %2;" : "=f"(lo), "=f"(hi) : "l"(v));
}
__device__ __forceinline__ void cp8(float* d, const float* s) {
#pragma unroll
    for (int k = 0; k < 8; ++k) d[k] = s[k];
}

// ---- 3-sample primitives (kernel 1) ----------------------------------------

__device__ __forceinline__ void leaf3(float4 qa, float4 qb, float4 qc,
                                      const float* __restrict__ w,
                                      float* hA, float* hB, float* hC) {
    ull cA0 = 0, cA1 = 0, cB0 = 0, cB1 = 0, cC0 = 0, cC1 = 0;
    float eA[2] = {qa.x, qa.y}, oA[2] = {qa.z, qa.w};
    float eB[2] = {qb.x, qb.y}, oB[2] = {qb.z, qb.w};
    float eC[2] = {qc.x, qc.y}, oC[2] = {qc.z, qc.w};
#pragma unroll
    for (int i = 0; i < 2; ++i) {
#pragma unroll
        for (int j = 0; j < 2; ++j) {
            const ulonglong2 W = *reinterpret_cast<const ulonglong2*>(w + (i * 2 + j) * 4);
            ull p = bcast2(eA[i] * oA[j]);
            cA0 = ffma2(p, W.x, cA0);  cA1 = ffma2(p, W.y, cA1);
            p = bcast2(eB[i] * oB[j]);
            cB0 = ffma2(p, W.x, cB0);  cB1 = ffma2(p, W.y, cB1);
            p = bcast2(eC[i] * oC[j]);
            cC0 = ffma2(p, W.x, cC0);  cC1 = ffma2(p, W.y, cC1);
        }
    }
    unpack2(cA0, hA[0], hA[1]);  unpack2(cA1, hA[2], hA[3]);
    unpack2(cB0, hB[0], hB[1]);  unpack2(cB1, hB[2], hB[3]);
    unpack2(cC0, hC[0], hC[1]);  unpack2(cC1, hC[2], hC[3]);
}

__device__ __forceinline__ void contract448_3(const float* aA, const float* bA,
                                              const float* aB, const float* bB,
                                              const float* aC, const float* bC,
                                              const float* __restrict__ w,
                                              float* outA, float* outB, float* outC) {
    ull cA[4] = {0,0,0,0}, cB[4] = {0,0,0,0}, cC[4] = {0,0,0,0};
#pragma unroll
    for (int i = 0; i < 4; ++i) {
        ull tA[4] = {0,0,0,0}, tB[4] = {0,0,0,0}, tC[4] = {0,0,0,0};
#pragma unroll
        for (int j = 0; j < 4; ++j) {
            const ulonglong2* wp = reinterpret_cast<const ulonglong2*>(w + (i * 4 + j) * 8);
            ulonglong2 W01 = wp[0];
            ulonglong2 W23 = wp[1];
            ull bb = bcast2(bA[j]);
            tA[0] = ffma2(bb, W01.x, tA[0]);  tA[1] = ffma2(bb, W01.y, tA[1]);
            tA[2] = ffma2(bb, W23.x, tA[2]);  tA[3] = ffma2(bb, W23.y, tA[3]);
            bb = bcast2(bB[j]);
            tB[0] = ffma2(bb, W01.x, tB[0]);  tB[1] = ffma2(bb, W01.y, tB[1]);
            tB[2] = ffma2(bb, W23.x, tB[2]);  tB[3] = ffma2(bb, W23.y, tB[3]);
            bb = bcast2(bC[j]);
            tC[0] = ffma2(bb, W01.x, tC[0]);  tC[1] = ffma2(bb, W01.y, tC[1]);
            tC[2] = ffma2(bb, W23.x, tC[2]);  tC[3] = ffma2(bb, W23.y, tC[3]);
        }
        ull ai = bcast2(aA[i]);
        cA[0] = ffma2(ai, tA[0], cA[0]);  cA[1] = ffma2(ai, tA[1], cA[1]);
        cA[2] = ffma2(ai, tA[2], cA[2]);  cA[3] = ffma2(ai, tA[3], cA[3]);
        ai = bcast2(aB[i]);
        cB[0] = ffma2(ai, tB[0], cB[0]);  cB[1] = ffma2(ai, tB[1], cB[1]);
        cB[2] = ffma2(ai, tB[2], cB[2]);  cB[3] = ffma2(ai, tB[3], cB[3]);
        ai = bcast2(aC[i]);
        cC[0] = ffma2(ai, tC[0], cC[0]);  cC[1] = ffma2(ai, tC[1], cC[1]);
        cC[2] = ffma2(ai, tC[2], cC[2]);  cC[3] = ffma2(ai, tC[3], cC[3]);
    }
    unpack2(cA[0], outA[0], outA[1]);  unpack2(cA[1], outA[2], outA[3]);
    unpack2(cA[2], outA[4], outA[5]);  unpack2(cA[3], outA[6], outA[7]);
    unpack2(cB[0], outB[0], outB[1]);  unpack2(cB[1], outB[2], outB[3]);
    unpack2(cB[2], outB[4], outB[5]);  unpack2(cB[3], outB[6], outB[7]);
    unpack2(cC[0], outC[0], outC[1]);  unpack2(cC[1], outC[2], outC[3]);
    unpack2(cC[2], outC[4], outC[5]);  unpack2(cC[3], outC[6], outC[7]);
}

// 8x8->8, three samples sharing W (512 floats, smem), prefetch distance 2.
// out may alias b.
__device__ __forceinline__ void contract888_3(const float* aA, const float* bA,
                                              const float* aB, const float* bB,
                                              const float* aC, const float* bC,
                                              const float* __restrict__ w,
                                              float* outA, float* outB, float* outC) {
    const ulonglong2* wp = reinterpret_cast<const ulonglong2*>(w);
    ull cA[4] = {0,0,0,0}, cB[4] = {0,0,0,0}, cC[4] = {0,0,0,0};
    ulonglong2 W0a = wp[0], W0b = wp[1];
    ulonglong2 W1a = wp[2], W1b = wp[3];
#pragma unroll
    for (int i = 0; i < 8; ++i) {
        ull tA[4] = {0,0,0,0}, tB[4] = {0,0,0,0}, tC[4] = {0,0,0,0};
#pragma unroll
        for (int j = 0; j < 8; ++j) {
            const int nidx = i * 8 + j + 2;
            ulonglong2 nWa, nWb;
            if (nidx < 64) {
                nWa = wp[2 * nidx];
                nWb = wp[2 * nidx + 1];
            }
            ull bb = bcast2(bA[j]);
            tA[0] = ffma2(bb, W0a.x, tA[0]);  tA[1] = ffma2(bb, W0a.y, tA[1]);
            tA[2] = ffma2(bb, W0b.x, tA[2]);  tA[3] = ffma2(bb, W0b.y, tA[3]);
            bb = bcast2(bB[j]);
            tB[0] = ffma2(bb, W0a.x, tB[0]);  tB[1] = ffma2(bb, W0a.y, tB[1]);
            tB[2] = ffma2(bb, W0b.x, tB[2]);  tB[3] = ffma2(bb, W0b.y, tB[3]);
            bb = bcast2(bC[j]);
            tC[0] = ffma2(bb, W0a.x, tC[0]);  tC[1] = ffma2(bb, W0a.y, tC[1]);
            tC[2] = ffma2(bb, W0b.x, tC[2]);  tC[3] = ffma2(bb, W0b.y, tC[3]);
            W0a = W1a;  W0b = W1b;
            if (nidx < 64) { W1a = nWa; W1b = nWb; }
        }
        ull ai = bcast2(aA[i]);
        cA[0] = ffma2(ai, tA[0], cA[0]);  cA[1] = ffma2(ai, tA[1], cA[1]);
        cA[2] = ffma2(ai, tA[2], cA[2]);  cA[3] = ffma2(ai, tA[3], cA[3]);
        ai = bcast2(aB[i]);
        cB[0] = ffma2(ai, tB[0], cB[0]);  cB[1] = ffma2(ai, tB[1], cB[1]);
        cB[2] = ffma2(ai, tB[2], cB[2]);  cB[3] = ffma2(ai, tB[3], cB[3]);
        ai = bcast2(aC[i]);
        cC[0] = ffma2(ai, tC[0], cC[0]);  cC[1] = ffma2(ai, tC[1], cC[1]);
        cC[2] = ffma2(ai, tC[2], cC[2]);  cC[3] = ffma2(ai, tC[3], cC[3]);
    }
    unpack2(cA[0], outA[0], outA[1]);  unpack2(cA[1], outA[2], outA[3]);
    unpack2(cA[2], outA[4], outA[5]);  unpack2(cA[3], outA[6], outA[7]);
    unpack2(cB[0], outB[0], outB[1]);  unpack2(cB[1], outB[2], outB[3]);
    unpack2(cB[2], outB[4], outB[5]);  unpack2(cB[3], outB[6], outB[7]);
    unpack2(cC[0], outC[0], outC[1]);  unpack2(cC[1], outC[2], outC[3]);
    unpack2(cC[2], outC[4], outC[5]);  unpack2(cC[3], outC[6], outC[7]);
}

// ---- 2-sample and 1-sample 8x8x8 (merge kernel) -----------------------------
__device__ __forceinline__ void contract888_2(const float* aA, const float* bA,
                                              const float* aB, const float* bB,
                                              const float* __restrict__ w,
                                              float* outA, float* outB) {
    const ulonglong2* wp = reinterpret_cast<const ulonglong2*>(w);
    ull cA[4] = {0,0,0,0}, cB[4] = {0,0,0,0};
    ulonglong2 W0a = wp[0], W0b = wp[1];
    ulonglong2 W1a = wp[2], W1b = wp[3];
#pragma unroll
    for (int i = 0; i < 8; ++i) {
        ull tA[4] = {0,0,0,0}, tB[4] = {0,0,0,0};
#pragma unroll
        for (int j = 0; j < 8; ++j) {
            const int nidx = i * 8 + j + 2;
            ulonglong2 nWa, nWb;
            if (nidx < 64) {
                nWa = wp[2 * nidx];
                nWb = wp[2 * nidx + 1];
            }
            ull bb = bcast2(bA[j]);
            tA[0] = ffma2(bb, W0a.x, tA[0]);  tA[1] = ffma2(bb, W0a.y, tA[1]);
            tA[2] = ffma2(bb, W0b.x, tA[2]);  tA[3] = ffma2(bb, W0b.y, tA[3]);
            bb = bcast2(bB[j]);
            tB[0] = ffma2(bb, W0a.x, tB[0]);  tB[1] = ffma2(bb, W0a.y, tB[1]);
            tB[2] = ffma2(bb, W0b.x, tB[2]);  tB[3] = ffma2(bb, W0b.y, tB[3]);
            W0a = W1a;  W0b = W1b;
            if (nidx < 64) { W1a = nWa; W1b = nWb; }
        }
        ull ai = bcast2(aA[i]);
        cA[0] = ffma2(ai, tA[0], cA[0]);  cA[1] = ffma2(ai, tA[1], cA[1]);
        cA[2] = ffma2(ai, tA[2], cA[2]);  cA[3] = ffma2(ai, tA[3], cA[3]);
        ai = bcast2(aB[i]);
        cB[0] = ffma2(ai, tB[0], cB[0]);  cB[1] = ffma2(ai, tB[1], cB[1]);
        cB[2] = ffma2(ai, tB[2], cB[2]);  cB[3] = ffma2(ai, tB[3], cB[3]);
    }
    unpack2(cA[0], outA[0], outA[1]);  unpack2(cA[1], outA[2], outA[3]);
    unpack2(cA[2], outA[4], outA[5]);  unpack2(cA[3], outA[6], outA[7]);
    unpack2(cB[0], outB[0], outB[1]);  unpack2(cB[1], outB[2], outB[3]);
    unpack2(cB[2], outB[4], outB[5]);  unpack2(cB[3], outB[6], outB[7]);
}

__device__ __forceinline__ void contract888_1(const float* a, const float* b,
                                              const float* __restrict__ w, float* out) {
    const ulonglong2* wp = reinterpret_cast<const ulonglong2*>(w);
    ull c[4] = {0,0,0,0};
    ulonglong2 W0a = wp[0], W0b = wp[1];
    ulonglong2 W1a = wp[2], W1b = wp[3];
#pragma unroll
    for (int i = 0; i < 8; ++i) {
        ull t[4] = {0,0,0,0};
#pragma unroll
        for (int j = 0; j < 8; ++j) {
            const int nidx = i * 8 + j + 2;
            ulonglong2 nWa, nWb;
            if (nidx < 64) {
                nWa = wp[2 * nidx];
                nWb = wp[2 * nidx + 1];
            }
            ull bb = bcast2(b[j]);
            t[0] = ffma2(bb, W0a.x, t[0]);  t[1] = ffma2(bb, W0a.y, t[1]);
            t[2] = ffma2(bb, W0b.x, t[2]);  t[3] = ffma2(bb, W0b.y, t[3]);
            W0a = W1a;  W0b = W1b;
            if (nidx < 64) { W1a = nWa; W1b = nWb; }
        }
        ull ai = bcast2(a[i]);
        c[0] = ffma2(ai, t[0], c[0]);  c[1] = ffma2(ai, t[1], c[1]);
        c[2] = ffma2(ai, t[2], c[2]);  c[3] = ffma2(ai, t[3], c[3]);
    }
    unpack2(c[0], out[0], out[1]);  unpack2(c[1], out[2], out[3]);
    unpack2(c[2], out[4], out[5]);  unpack2(c[3], out[6], out[7]);
}

__device__ __forceinline__ void scopy4(float* dst, const float* __restrict__ src, int n4) {
    const float4* s = reinterpret_cast<const float4*>(src);
    float4* d = reinterpret_cast<float4*>(dst);
    for (int i = threadIdx.x; i < n4; i += blockDim.x) d[i] = s[i];
}

__device__ __forceinline__ void store_pair(float4* buf, int b, const float* v) {
    buf[(size_t)b * 2 + 0] = make_float4(v[0], v[1], v[2], v[3]);
    buf[(size_t)b * 2 + 1] = make_float4(v[4], v[5], v[6], v[7]);
}

// ------------------------------- kernel 1 ----------------------------------
__global__ void __launch_bounds__(T1, 5)
tn_eighth_kernel(const float* __restrict__ x,
                 const float* __restrict__ w7, const float* __restrict__ w6,
                 const float* __restrict__ w5, const float* __restrict__ w4,
                 const float* __restrict__ w3) {
    extern __shared__ float sw[];

    const int e   = blockIdx.x / BLK_E;      // eighth 0..7
    const int blk = blockIdx.x - e * BLK_E;  // 0..341

    scopy4(sw + E7, w7 + e * 256,   256 / 4);
    scopy4(sw + E6, w6 + e * 1024, 1024 / 4);
    scopy4(sw + E5, w5 + e * 2048, 2048 / 4);
    scopy4(sw + E4, w4 + e * 1024, 1024 / 4);
    scopy4(sw + E3, w3 + e * 512,   512 / 4);
    __syncthreads();

    const int b0 = blk * SPB + threadIdx.x;
    int b1 = b0 + T1;
    int b2 = b0 + 2 * T1;
    if (b1 >= NB) b1 = b0;
    if (b2 >= NB) b2 = b0;

    const float4* xA = reinterpret_cast<const float4*>(x) + (size_t)b0 * 128 + e * 16;
    const float4* xB = reinterpret_cast<const float4*>(x) + (size_t)b1 * 128 + e * 16;
    const float4* xC = reinterpret_cast<const float4*>(x) + (size_t)b2 * 128 + e * 16;

    float stkA0[8], stkA1[8], stkA2[8];
    float stkB0[8], stkB1[8], stkB2[8];
    float stkC0[8], stkC1[8], stkC2[8];

#pragma unroll 1
    for (int m = 0; m < 8; ++m) {
        // streaming (evict-first) x loads: protect g_ebuf's L2 residency
        float4 qA0 = __ldcs(xA + 2 * m);
        float4 qA1 = __ldcs(xA + 2 * m + 1);
        float4 qB0 = __ldcs(xB + 2 * m);
        float4 qB1 = __ldcs(xB + 2 * m + 1);
        float4 qC0 = __ldcs(xC + 2 * m);
        float4 qC1 = __ldcs(xC + 2 * m + 1);

        float laA[4], lbA[4], laB[4], lbB[4], laC[4], lbC[4];
        leaf3(qA0, qB0, qC0, sw + E7 + (2 * m) * 16, laA, laB, laC);
        leaf3(qA1, qB1, qC1, sw + E7 + (2 * m + 1) * 16, lbA, lbB, lbC);

        float curA[8], curB[8], curC[8];
        contract448_3(laA, lbA, laB, lbB, laC, lbC, sw + E6 + m * 128,
                      curA, curB, curC);

        if (!(m & 1)) {
            cp8(stkA0, curA);  cp8(stkB0, curB);  cp8(stkC0, curC);
        } else {
            contract888_3(stkA0, curA, stkB0, curB, stkC0, curC,
                          sw + E5 + (m >> 1) * 512, curA, curB, curC);
            if (!((m >> 1) & 1)) {
                cp8(stkA1, curA);  cp8(stkB1, curB);  cp8(stkC1, curC);
            } else {
                contract888_3(stkA1, curA, stkB1, curB, stkC1, curC,
                              sw + E4 + (m >> 2) * 512, curA, curB, curC);
                if (!((m >> 2) & 1)) {
                    cp8(stkA2, curA);  cp8(stkB2, curB);  cp8(stkC2, curC);
                } else {
                    // m == 7: top of this eighth (w3 node)
                    contract888_3(stkA2, curA, stkB2, curB, stkC2, curC,
                                  sw + E3, curA, curB, curC);
                    float4* eb = g_ebuf + ((size_t)e * NB) * 2;
                    store_pair(eb, b0, curA);
                    store_pair(eb, b1, curB);
                    store_pair(eb, b2, curC);
                }
            }
        }
    }
}

// ------------------------------- kernel 2 ----------------------------------
// 4 warps per CTA, 32 sample-pairs per CTA, grid 1024. g_ebuf loads hoisted
// above the weight staging (overlap LDG latency with smem staging + sync).
__global__ void __launch_bounds__(T2)
tn_merge_kernel(const float* __restrict__ w2, const float* __restrict__ w1,
                const float* __restrict__ w0, float* __restrict__ out) {
    __shared__ float w2s[2048];
    __shared__ float w1s[1024];
    __shared__ float w0s[128];
    __shared__ float x1[4][2][32 * 9];   // stage1: [w2 node][class A/B][lane]
    __shared__ float x2[2][2][32 * 9];   // stage2: [side L/R][class A/B][lane]

    const int warp = threadIdx.x >> 5;
    const int lane = threadIdx.x & 31;
    const int bA = blockIdx.x * 32 + lane;
    const int bB = bA + HALF;

    // hoisted g_ebuf loads (8 independent LDG.128 per thread)
    float4 pA0 = __ldg(g_ebuf + ((size_t)(2 * warp + 0) * NB + bA) * 2 + 0);
    float4 pA1 = __ldg(g_ebuf + ((size_t)(2 * warp + 0) * NB + bA) * 2 + 1);
    float4 pA2 = __ldg(g_ebuf + ((size_t)(2 * warp + 1) * NB + bA) * 2 + 0);
    float4 pA3 = __ldg(g_ebuf + ((size_t)(2 * warp + 1) * NB + bA) * 2 + 1);
    float4 pB0 = __ldg(g_ebuf + ((size_t)(2 * warp + 0) * NB + bB) * 2 + 0);
    float4 pB1 = __ldg(g_ebuf + ((size_t)(2 * warp + 0) * NB + bB) * 2 + 1);
    float4 pB2 = __ldg(g_ebuf + ((size_t)(2 * warp + 1) * NB + bB) * 2 + 0);
    float4 pB3 = __ldg(g_ebuf + ((size_t)(2 * warp + 1) * NB + bB) * 2 + 1);

    scopy4(w2s, w2, 2048 / 4);
    scopy4(w1s, w1, 1024 / 4);
    scopy4(w0s, w0, 128 / 4);
    __syncthreads();

    // ---- stage 1: w2 node = warp (eighths 2*warp, 2*warp+1) ----
    {
        float vA0[8] = {pA0.x, pA0.y, pA0.z, pA0.w, pA1.x, pA1.y, pA1.z, pA1.w};
        float vA1[8] = {pA2.x, pA2.y, pA2.z, pA2.w, pA3.x, pA3.y, pA3.z, pA3.w};
        float vB0[8] = {pB0.x, pB0.y, pB0.z, pB0.w, pB1.x, pB1.y, pB1.z, pB1.w};
        float vB1[8] = {pB2.x, pB2.y, pB2.z, pB2.w, pB3.x, pB3.y, pB3.z, pB3.w};
        float qA[8], qB[8];
        contract888_2(vA0, vA1, vB0, vB1, w2s + warp * 512, qA, qB);
#pragma unroll
        for (int k = 0; k < 8; ++k) {
            x1[warp][0][lane * 9 + k] = qA[k];
            x1[warp][1][lane * 9 + k] = qB[k];
        }
    }
    __syncthreads();

    // ---- stage 2: one w1 eval per warp ----
    const int side = warp >> 1;
    const int cls  = warp & 1;
    {
        float a[8], b[8], h[8];
#pragma unroll
        for (int k = 0; k < 8; ++k) {
            a[k] = x1[2 * side + 0][cls][lane * 9 + k];
            b[k] = x1[2 * side + 1][cls][lane * 9 + k];
        }
        contract888_1(a, b, w1s + side * 512, h);
#pragma unroll
        for (int k = 0; k < 8; ++k) x2[side][cls][lane * 9 + k] = h[k];
    }
    __syncthreads();

    // ---- stage 3: roots (warp 0 -> sample A, warp 1 -> sample B) ----
    if (warp < 2) {
        const int c  = warp;
        const int bo = c == 0 ? bA : bB;
        float hL[8], hR[8];
#pragma unroll
        for (int k = 0; k < 8; ++k) {
            hL[k] = x2[0][c][lane * 9 + k];
            hR[k] = x2[1][c][lane * 9 + k];
        }
        ull acc = 0ull;
#pragma unroll
        for (int i = 0; i < 8; ++i) {
            ull ai = bcast2(hL[i]);
#pragma unroll
            for (int j = 0; j < 8; ++j) {
                ull W = *reinterpret_cast<const ull*>(w0s + (i * 8 + j) * 2);
                acc = ffma2(ffma2(ai, bcast2(hR[j]), 0ull), W, acc);
            }
        }
        float r0, r1;
        unpack2(acc, r0, r1);
        reinterpret_cast<float2*>(out)[bo] = make_float2(r0, r1);
    }
}

extern "C" void kernel_launch(void* const* d_in, const int* in_sizes, int n_in,
                              void* d_out, int out_size) {
    const float* x  = (const float*)d_in[0];
    const float* w7 = (const float*)d_in[1];
    const float* w6 = (const float*)d_in[2];
    const float* w5 = (const float*)d_in[3];
    const float* w4 = (const float*)d_in[4];
    const float* w3 = (const float*)d_in[5];
    const float* w2 = (const float*)d_in[6];
    const float* w1 = (const float*)d_in[7];
    const float* w0 = (const float*)d_in[8];
    float* out = (float*)d_out;

    const size_t smem = SMEM1_FLOATS * sizeof(float);
    cudaFuncSetAttribute(tn_eighth_kernel, cudaFuncAttributeMaxDynamicSharedMemorySize, (int)smem);
    tn_eighth_kernel<<<NBLOCKS1, T1, smem>>>(x, w7, w6, w5, w4, w3);
    tn_merge_kernel<<<NBLOCKS2, T2>>>(w2, w1, w0, out);
}